// round 1
// baseline (speedup 1.0000x reference)
#include <cuda_runtime.h>
#include <math.h>

#define N_ELEC 8192
#define N_NUC  512
#define EMB    256
#define KER    256
#define DF     64
#define MID    128

// ---------------- scratch (device globals; no allocations allowed) ----------
__device__ float g_HX[N_ELEC * KER];          // electrons @ h_w      (8 MB)
__device__ float g_Z[N_ELEC * 3 * KER];       // scatter accumulators (24 MB)
__device__ float g_Gcat[3 * KER * EMB];       // [g_same; g_anti; g_n]

// ---------------- packed fp32x2 FMA (2x fp32 throughput on sm_103a) ---------
__device__ __forceinline__ float2 ffma2(float2 a, float2 b, float2 c) {
    union U { float2 f; unsigned long long u; };
    U A, B, C, D;
    A.f = a; B.f = b; C.f = c;
    asm("fma.rn.f32x2 %0, %1, %2, %3;" : "=l"(D.u) : "l"(A.u), "l"(B.u), "l"(C.u));
    return D.f;
}

// shifted softplus: log(0.5*exp(x)+0.5) = softplus(x) - ln 2 (stable form)
__device__ __forceinline__ float sspf(float x) {
    float sp = (x > 0.f) ? (x + log1pf(expf(-x))) : log1pf(expf(x));
    return sp - 0.69314718055994531f;
}

// ---------------- generic 128x128 tiled SGEMM: Out = (Cin?) + A@B -----------
// A: [M,K] row-major with leading dim lda; B: [K,N] row-major; tiles 128x128,
// BK=32, 256 threads, micro-tile 8x8 with strided mapping r=ty+16i, c=tx+16j
// (A smem loads are half-warp broadcasts; B loads 16 consecutive -> no conflicts)
__global__ void __launch_bounds__(256, 1)
sgemm128(const float* __restrict__ A, int lda,
         const float* __restrict__ B,
         const float* __restrict__ Cin,
         float* __restrict__ Out,
         int N, int K)
{
    __shared__ float sA[32 * 129];   // [k][m], padded
    __shared__ float sB[32 * 128];   // [k][n]
    const int t  = threadIdx.x;
    const int ty = t >> 4, tx = t & 15;
    const int m0 = blockIdx.y << 7, n0 = blockIdx.x << 7;

    float2 acc[8][4];
#pragma unroll
    for (int i = 0; i < 8; i++)
#pragma unroll
        for (int p = 0; p < 4; p++) acc[i][p] = make_float2(0.f, 0.f);

    for (int kc = 0; kc < K; kc += 32) {
#pragma unroll
        for (int m = 0; m < 16; m++) {
            int lin = m * 256 + t;
            int row = lin >> 5, col = lin & 31;
            sA[col * 129 + row] = A[(long)(m0 + row) * lda + kc + col];
        }
#pragma unroll
        for (int m = 0; m < 16; m++) {
            int lin = m * 256 + t;
            int row = lin >> 7, col = lin & 127;
            sB[row * 128 + col] = B[(long)(kc + row) * N + n0 + col];
        }
        __syncthreads();
#pragma unroll
        for (int kk = 0; kk < 32; kk++) {
            float a[8];
#pragma unroll
            for (int i = 0; i < 8; i++) a[i] = sA[kk * 129 + ty + 16 * i];
            float2 bp[4];
#pragma unroll
            for (int p = 0; p < 4; p++) {
                bp[p].x = sB[kk * 128 + tx + 32 * p];
                bp[p].y = sB[kk * 128 + tx + 32 * p + 16];
            }
#pragma unroll
            for (int i = 0; i < 8; i++) {
                float2 ap = make_float2(a[i], a[i]);
#pragma unroll
                for (int p = 0; p < 4; p++) acc[i][p] = ffma2(ap, bp[p], acc[i][p]);
            }
        }
        __syncthreads();
    }

#pragma unroll
    for (int i = 0; i < 8; i++) {
        int r = m0 + ty + 16 * i;
#pragma unroll
        for (int p = 0; p < 4; p++) {
            long i0 = (long)r * N + n0 + tx + 32 * p;
            long i1 = i0 + 16;
            float v0 = acc[i][p].x, v1 = acc[i][p].y;
            if (Cin) { v0 += Cin[i0]; v1 += Cin[i1]; }
            Out[i0] = v0; Out[i1] = v1;
        }
    }
}

// ---------------- fused edge kernel --------------------------------------
// Per block of 128 edges:
//   mid  = ssp(dist[128,64] @ w1[64,128] + b1)           (stage 1, smem)
//   we   = mid @ w2[128,256]                              (stage 2, w2 streamed)
//   Z[recv] += we * hxsrc[send]                           (stage 3, atomics)
#define SMEM_EDGE (1536 + 66048 + 32768)   // idx/b1 + union(distT+w1 | midT) + w2 chunk

__global__ void __launch_bounds__(256, 1)
edge_kernel(const float* __restrict__ dist,
            const float* __restrict__ w1,
            const float* __restrict__ b1,
            const float* __restrict__ w2,
            const float* __restrict__ hxsrc,   // HX [8192,256] or nuclei [512,256]
            const int*   __restrict__ senders,
            const int*   __restrict__ receivers,
            float* __restrict__ Z, int zoff)
{
    extern __shared__ char smem[];
    int*   sSend  = (int*)(smem);
    int*   sRecv  = (int*)(smem + 512);
    float* sB1    = (float*)(smem + 1024);
    float* sU     = (float*)(smem + 1536);
    float* sDistT = sU;                 // [64][129]  (phase A)
    float* sW1    = sU + 64 * 129;      // [64][128]  (phase A)
    float* sMidT  = sU;                 // [128][129] (phase B, reuses region)
    float* sW2    = (float*)(smem + 1536 + 66048);  // [32][256]

    const int  t  = threadIdx.x;
    const int  ty = t >> 4, tx = t & 15;
    const long e0 = (long)blockIdx.x * 128;

    if (t < 128) {
        sSend[t] = senders[e0 + t];
        sRecv[t] = receivers[e0 + t];
        sB1[t]   = b1[t];
    }
#pragma unroll
    for (int m = 0; m < 32; m++) {
        int lin = m * 256 + t;
        sDistT[(lin & 63) * 129 + (lin >> 6)] = dist[e0 * 64 + lin];  // transpose in
        sW1[lin] = w1[lin];
    }
    __syncthreads();

    // ---- stage 1: mid = dist @ w1 ----
    float2 acc1[8][4];
#pragma unroll
    for (int i = 0; i < 8; i++)
#pragma unroll
        for (int p = 0; p < 4; p++) acc1[i][p] = make_float2(0.f, 0.f);

#pragma unroll 4
    for (int k = 0; k < 64; k++) {
        float a[8];
#pragma unroll
        for (int i = 0; i < 8; i++) a[i] = sDistT[k * 129 + ty + 16 * i];
        float2 bp[4];
#pragma unroll
        for (int p = 0; p < 4; p++) {
            bp[p].x = sW1[k * 128 + tx + 32 * p];
            bp[p].y = sW1[k * 128 + tx + 32 * p + 16];
        }
#pragma unroll
        for (int i = 0; i < 8; i++) {
            float2 ap = make_float2(a[i], a[i]);
#pragma unroll
            for (int p = 0; p < 4; p++) acc1[i][p] = ffma2(ap, bp[p], acc1[i][p]);
        }
    }
    __syncthreads();   // all reads of sDistT/sW1 done

    // ---- bias + SSP, write mid transposed into smem ----
#pragma unroll
    for (int p = 0; p < 4; p++) {
        int c0 = tx + 32 * p, c1 = c0 + 16;
        float bb0 = sB1[c0], bb1 = sB1[c1];
#pragma unroll
        for (int i = 0; i < 8; i++) {
            int r = ty + 16 * i;
            sMidT[c0 * 129 + r] = sspf(acc1[i][p].x + bb0);
            sMidT[c1 * 129 + r] = sspf(acc1[i][p].y + bb1);
        }
    }
    __syncthreads();

    // ---- stage 2: we = mid @ w2 (w2 streamed in 32-row chunks) ----
    float2 acc2[8][8];
#pragma unroll
    for (int i = 0; i < 8; i++)
#pragma unroll
        for (int p = 0; p < 8; p++) acc2[i][p] = make_float2(0.f, 0.f);

    for (int kc = 0; kc < 128; kc += 32) {
#pragma unroll
        for (int m = 0; m < 32; m++) {
            int lin = m * 256 + t;
            sW2[lin] = w2[kc * 256 + lin];
        }
        __syncthreads();
#pragma unroll 2
        for (int kk = 0; kk < 32; kk++) {
            float a[8];
#pragma unroll
            for (int i = 0; i < 8; i++) a[i] = sMidT[(kc + kk) * 129 + ty + 16 * i];
            float2 bp[8];
#pragma unroll
            for (int p = 0; p < 8; p++) {
                bp[p].x = sW2[kk * 256 + tx + 32 * p];
                bp[p].y = sW2[kk * 256 + tx + 32 * p + 16];
            }
#pragma unroll
            for (int i = 0; i < 8; i++) {
                float2 ap = make_float2(a[i], a[i]);
#pragma unroll
                for (int p = 0; p < 8; p++) acc2[i][p] = ffma2(ap, bp[p], acc2[i][p]);
            }
        }
        __syncthreads();
    }

    // ---- stage 3: gather hx, multiply, scatter-add ----
#pragma unroll
    for (int i = 0; i < 8; i++) {
        int r = ty + 16 * i;
        const float* hx   = hxsrc + (long)sSend[r] * 256;
        float*       zrow = Z + (long)sRecv[r] * (3 * KER) + zoff;
#pragma unroll
        for (int p = 0; p < 8; p++) {
            int c0 = tx + 32 * p, c1 = c0 + 16;
            atomicAdd(zrow + c0, acc2[i][p].x * hx[c0]);
            atomicAdd(zrow + c1, acc2[i][p].y * hx[c1]);
        }
    }
}

// ---------------- launcher --------------------------------------------------
extern "C" void kernel_launch(void* const* d_in, const int* in_sizes, int n_in,
                              void* d_out, int out_size)
{
    const float* elec = (const float*)d_in[0];
    const float* nuc  = (const float*)d_in[1];
    const float *dist[3], *w1[3], *b1[3], *w2[3], *g[3];

    // Disambiguate input ordering at runtime:
    //  dict order:  in_sizes[3] = w1_same  = 64*128  = 8192
    //  sig  order:  in_sizes[3] = dist_anti = 131072*64
    bool dictOrder = (in_sizes[3] == DF * MID);
    if (dictOrder) {
        const int base[3] = {2, 7, 12};
        for (int tI = 0; tI < 3; tI++) {
            dist[tI] = (const float*)d_in[base[tI] + 0];
            w1[tI]   = (const float*)d_in[base[tI] + 1];
            b1[tI]   = (const float*)d_in[base[tI] + 2];
            w2[tI]   = (const float*)d_in[base[tI] + 3];
            g[tI]    = (const float*)d_in[base[tI] + 4];
        }
    } else {
        for (int tI = 0; tI < 3; tI++) {
            dist[tI] = (const float*)d_in[2 + tI];
            w1[tI]   = (const float*)d_in[5 + 3 * tI];
            b1[tI]   = (const float*)d_in[6 + 3 * tI];
            w2[tI]   = (const float*)d_in[7 + 3 * tI];
            g[tI]    = (const float*)d_in[14 + tI];
        }
    }
    const float* h_w    = (const float*)d_in[17];
    const int*   send[3] = {(const int*)d_in[18], (const int*)d_in[19], (const int*)d_in[20]};
    const int*   recv[3] = {(const int*)d_in[21], (const int*)d_in[22], (const int*)d_in[23]};
    const int    E = in_sizes[2] / DF;   // dist_same is index 2 in both orderings

    float *HX, *Z, *Gcat;
    cudaGetSymbolAddress((void**)&HX,   g_HX);
    cudaGetSymbolAddress((void**)&Z,    g_Z);
    cudaGetSymbolAddress((void**)&Gcat, g_Gcat);

    cudaFuncSetAttribute(edge_kernel, cudaFuncAttributeMaxDynamicSharedMemorySize, SMEM_EDGE);

    cudaMemsetAsync(Z, 0, sizeof(float) * N_ELEC * 3 * KER);
    for (int tI = 0; tI < 3; tI++)
        cudaMemcpyAsync(Gcat + tI * KER * EMB, g[tI], sizeof(float) * KER * EMB,
                        cudaMemcpyDeviceToDevice);

    // HX = electrons @ h_w   [8192,256]
    {
        dim3 grid(KER / 128, N_ELEC / 128);
        sgemm128<<<grid, 256>>>(elec, EMB, h_w, nullptr, HX, KER, EMB);
    }

    // fused per-edge MLP + gather + scatter (3 edge types)
    for (int tI = 0; tI < 3; tI++) {
        const float* hxsrc = (tI == 2) ? nuc : HX;
        edge_kernel<<<E / 128, 256, SMEM_EDGE>>>(dist[tI], w1[tI], b1[tI], w2[tI],
                                                 hxsrc, send[tI], recv[tI], Z, tI * KER);
    }

    // out = electrons + Z @ Gcat   [8192,256]
    {
        dim3 grid(EMB / 128, N_ELEC / 128);
        sgemm128<<<grid, 256>>>(Z, 3 * KER, Gcat, elec, (float*)d_out, EMB, 3 * KER);
    }
}

// round 4
// speedup vs baseline: 1.4143x; 1.4143x over previous
#include <cuda_runtime.h>
#include <math.h>
#include <stdint.h>

#define N_ELEC 8192
#define N_NUC  512
#define EMB    256
#define KER    256
#define DF     64
#define MID    128

// ---------------- scratch (device globals; no allocations allowed) ----------
__device__ __align__(16) float g_HX[N_ELEC * KER];       // electrons @ h_w
__device__ __align__(16) float g_Z[N_ELEC * 3 * KER];    // scatter accumulators
__device__ __align__(16) float g_Gcat[3 * KER * EMB];    // [g_same; g_anti; g_n]
// pre-transposed, k-pair-permuted, tf32-rounded weight images
__device__ __align__(16) float g_w1T[3][128 * 72];            // stride 72
__device__ __align__(16) float g_w2T[3][2][128 * 136];        // stride 136, 2 N-halves

// ---------------- helpers ---------------------------------------------------
__device__ __forceinline__ uint32_t tf32r(float x) {
    uint32_t u;
    asm("cvt.rna.tf32.f32 %0, %1;" : "=r"(u) : "f"(x));
    return u;
}
__device__ __forceinline__ float tf32f(float x) { return __uint_as_float(tf32r(x)); }

// k-pair permutation: puts (k, k+4) adjacent within each 8-group
__device__ __host__ __forceinline__ int kperm(int k) {
    return (k & ~7) | (((k & 3) << 1) | ((k >> 2) & 1));
}

__device__ __forceinline__ void mma_tf32(float acc[4], uint32_t a0, uint32_t a1,
                                         uint32_t a2, uint32_t a3,
                                         uint32_t b0, uint32_t b1) {
    asm volatile(
        "mma.sync.aligned.m16n8k8.row.col.f32.tf32.tf32.f32 "
        "{%0,%1,%2,%3}, {%4,%5,%6,%7}, {%8,%9}, {%0,%1,%2,%3};"
        : "+f"(acc[0]), "+f"(acc[1]), "+f"(acc[2]), "+f"(acc[3])
        : "r"(a0), "r"(a1), "r"(a2), "r"(a3), "r"(b0), "r"(b1));
}
__device__ __forceinline__ void red2(float* p, float x, float y) {
    asm volatile("red.global.add.v2.f32 [%0], {%1, %2};" :: "l"(p), "f"(x), "f"(y) : "memory");
}

__device__ __forceinline__ float2 ffma2(float2 a, float2 b, float2 c) {
    union U { float2 f; unsigned long long u; };
    U A, B, C, D; A.f = a; B.f = b; C.f = c;
    asm("fma.rn.f32x2 %0, %1, %2, %3;" : "=l"(D.u) : "l"(A.u), "l"(B.u), "l"(C.u));
    return D.f;
}
__device__ __forceinline__ float sspf(float x) {
    float sp = (x > 0.f) ? (x + log1pf(expf(-x))) : log1pf(expf(x));
    return sp - 0.69314718055994531f;
}

// ================= weight prep: transpose + permute + tf32 ==================
__global__ void prep_weights(const float* __restrict__ w1_0, const float* __restrict__ w1_1,
                             const float* __restrict__ w1_2,
                             const float* __restrict__ w2_0, const float* __restrict__ w2_1,
                             const float* __restrict__ w2_2)
{
    int ty = blockIdx.x;
    const float* w1 = (ty == 0) ? w1_0 : (ty == 1) ? w1_1 : w1_2;
    const float* w2 = (ty == 0) ? w2_0 : (ty == 1) ? w2_1 : w2_2;
    // w1 [64,128] -> w1T[n][perm(k)], stride 72
    for (int i = threadIdx.x; i < 128 * 64; i += blockDim.x) {
        int n = i >> 6, k = i & 63;
        g_w1T[ty][n * 72 + kperm(k)] = tf32f(w1[k * 128 + n]);
    }
    // w2 [128,256] -> per N-half: w2T[h][nn][perm(k)], stride 136
    for (int i = threadIdx.x; i < 256 * 128; i += blockDim.x) {
        int n = i >> 7, k = i & 127;
        int h = n >> 7, nn = n & 127;
        g_w2T[ty][h][nn * 136 + kperm(k)] = tf32f(w2[k * 256 + n]);
    }
}

// ================= fused mma.sync tf32 edge kernel ==========================
// smem (floats unless noted):
//   header 1536B:  b1[128] @0,  send[128] @512,  recv[128] @1024
//   SM_DIST 1536:   dist tile [128][72]  (36864B)          | region A, later
//   SM_W1T  38400:  w1T  tile [128][72]  (36864B)          | overlaid by w2T-h1
//   SM_MID  75264:  mid  tile [128][136] (69632B)
//   SM_W2H0 144896: w2T half0 [128][136] (69632B)
#define SM_B1    0
#define SM_SEND  512
#define SM_RECV  1024
#define SM_DIST  1536
#define SM_W1T   38400
#define SM_W2H1  1536
#define SM_MID   75264
#define SM_W2H0  144896
#define SMEM_EDGE 214528

__global__ void __launch_bounds__(256, 1)
edge_mma(const float* __restrict__ dist,
         const float* __restrict__ b1,
         const float* __restrict__ w1T,       // [128*72]
         const float* __restrict__ w2T,       // [2][128*136]
         const float* __restrict__ hxsrc,     // HX [8192,256] or nuclei [512,256]
         const int*   __restrict__ senders,
         const int*   __restrict__ receivers,
         float* __restrict__ Z, int zoff)
{
    extern __shared__ char smem[];
    float* smF = (float*)smem;
    const int t = threadIdx.x, warp = t >> 5, lane = t & 31;
    const int g = lane >> 2, c = lane & 3;
    const int r0 = warp * 16;
    const long e0 = (long)blockIdx.x * 128;

    // ---- fill phase ----
    if (t < 128) {
        smF[(SM_B1 >> 2) + t]   = b1[t];
        ((int*)smem)[(SM_SEND >> 2) + t] = senders[e0 + t];
        ((int*)smem)[(SM_RECV >> 2) + t] = receivers[e0 + t];
    }
    {
        const float4* s1 = (const float4*)w1T;
        float4* d1 = (float4*)(smem + SM_W1T);
#pragma unroll
        for (int i = 0; i < 9; i++) d1[t + 256 * i] = s1[t + 256 * i];
        const float4* s2 = (const float4*)w2T;
        float4* d2 = (float4*)(smem + SM_W2H0);
#pragma unroll
        for (int i = 0; i < 17; i++) d2[t + 256 * i] = s2[t + 256 * i];
        // dist: convert to tf32 + k-pair permute; thread pair per row
        int row = t >> 1, half32 = t & 1;
        const float4* dr = (const float4*)(dist + (e0 + row) * DF);
        float* dst = smF + (SM_DIST >> 2) + row * 72;
#pragma unroll
        for (int j = 0; j < 8; j++) {
            int c4 = half32 * 8 + j;
            float4 v = dr[c4];
            int k = c4 * 4;
            dst[kperm(k + 0)] = tf32f(v.x);
            dst[kperm(k + 1)] = tf32f(v.y);
            dst[kperm(k + 2)] = tf32f(v.z);
            dst[kperm(k + 3)] = tf32f(v.w);
        }
    }
    __syncthreads();

    // ---- stage 1: acc1 = dist @ w1  (per warp: rows r0..r0+15, all 128 cols)
    float acc1[16][4];
#pragma unroll
    for (int nt = 0; nt < 16; nt++)
#pragma unroll
        for (int q = 0; q < 4; q++) acc1[nt][q] = 0.f;

    {
        const float* smD = smF + (SM_DIST >> 2);
        const float* smB = smF + (SM_W1T >> 2);
#pragma unroll
        for (int s = 0; s < 8; s++) {
            int kq = 8 * s + 2 * c;
            float2 aA = *(const float2*)(smD + (r0 + g) * 72 + kq);
            float2 aB = *(const float2*)(smD + (r0 + g + 8) * 72 + kq);
            uint32_t a0 = __float_as_uint(aA.x), a2 = __float_as_uint(aA.y);
            uint32_t a1 = __float_as_uint(aB.x), a3 = __float_as_uint(aB.y);
#pragma unroll
            for (int nt = 0; nt < 16; nt++) {
                float2 bb = *(const float2*)(smB + (nt * 8 + g) * 72 + kq);
                mma_tf32(acc1[nt], a0, a1, a2, a3,
                         __float_as_uint(bb.x), __float_as_uint(bb.y));
            }
        }
    }
    __syncthreads();   // everyone done reading dist/w1T region

    // ---- overlay w2T half-1 over region A; write bias+SSP mid tile ----
    {
        const float4* s3 = (const float4*)(w2T + 128 * 136);
        float4* d3 = (float4*)(smem + SM_W2H1);
#pragma unroll
        for (int i = 0; i < 17; i++) d3[t + 256 * i] = s3[t + 256 * i];
    }
    {
        float* smM = smF + (SM_MID >> 2);
        const float* sB1 = smF + (SM_B1 >> 2);
        int ra = r0 + g, rb = r0 + g + 8;
        int p0 = ((2 * c) & 3) * 2 + (((2 * c) >> 2) & 1);          // perm of 2c
        int p1 = ((2 * c + 1) & 3) * 2 + (((2 * c + 1) >> 2) & 1);  // perm of 2c+1
#pragma unroll
        for (int nt = 0; nt < 16; nt++) {
            int col = nt * 8 + 2 * c;
            float bb0 = sB1[col], bb1 = sB1[col + 1];
            smM[ra * 136 + nt * 8 + p0] = tf32f(sspf(acc1[nt][0] + bb0));
            smM[ra * 136 + nt * 8 + p1] = tf32f(sspf(acc1[nt][1] + bb1));
            smM[rb * 136 + nt * 8 + p0] = tf32f(sspf(acc1[nt][2] + bb0));
            smM[rb * 136 + nt * 8 + p1] = tf32f(sspf(acc1[nt][3] + bb1));
        }
    }
    __syncthreads();

    // ---- stage 2 (two N-halves): we = mid @ w2half; epilogue per half ----
    const int ra = r0 + g, rb = r0 + g + 8;
    const int sa = ((int*)smem)[(SM_SEND >> 2) + ra];
    const int sb = ((int*)smem)[(SM_SEND >> 2) + rb];
    const int qa = ((int*)smem)[(SM_RECV >> 2) + ra];
    const int qb = ((int*)smem)[(SM_RECV >> 2) + rb];
    const float* hxa = hxsrc + (long)sa * KER;
    const float* hxb = hxsrc + (long)sb * KER;
    float* Za = Z + (long)qa * (3 * KER) + zoff;
    float* Zb = Z + (long)qb * (3 * KER) + zoff;

#pragma unroll
    for (int h = 0; h < 2; h++) {
        const float* smB = smF + ((h == 0 ? SM_W2H0 : SM_W2H1) >> 2);
        const float* smM = smF + (SM_MID >> 2);
        float acc2[16][4];
#pragma unroll
        for (int nt = 0; nt < 16; nt++)
#pragma unroll
            for (int q = 0; q < 4; q++) acc2[nt][q] = 0.f;

#pragma unroll 4
        for (int s = 0; s < 16; s++) {
            int kq = 8 * s + 2 * c;
            float2 aA = *(const float2*)(smM + ra * 136 + kq);
            float2 aB = *(const float2*)(smM + rb * 136 + kq);
            uint32_t a0 = __float_as_uint(aA.x), a2 = __float_as_uint(aA.y);
            uint32_t a1 = __float_as_uint(aB.x), a3 = __float_as_uint(aB.y);
#pragma unroll
            for (int nt = 0; nt < 16; nt++) {
                float2 bb = *(const float2*)(smB + (nt * 8 + g) * 136 + kq);
                mma_tf32(acc2[nt], a0, a1, a2, a3,
                         __float_as_uint(bb.x), __float_as_uint(bb.y));
            }
        }
        // epilogue: weh = we * hx[sender]; v2 red to Z[receiver]
#pragma unroll
        for (int nt = 0; nt < 16; nt++) {
            int col = h * 128 + nt * 8 + 2 * c;
            float2 ha = *(const float2*)(hxa + col);
            red2(Za + col, acc2[nt][0] * ha.x, acc2[nt][1] * ha.y);
            float2 hb = *(const float2*)(hxb + col);
            red2(Zb + col, acc2[nt][2] * hb.x, acc2[nt][3] * hb.y);
        }
    }
}

// ---------------- generic 128x128 tiled fp32 SGEMM (unchanged, passing) -----
__global__ void __launch_bounds__(256, 1)
sgemm128(const float* __restrict__ A, int lda,
         const float* __restrict__ B,
         const float* __restrict__ Cin,
         float* __restrict__ Out,
         int N, int K)
{
    __shared__ float sA[32 * 129];
    __shared__ float sB[32 * 128];
    const int t  = threadIdx.x;
    const int ty = t >> 4, tx = t & 15;
    const int m0 = blockIdx.y << 7, n0 = blockIdx.x << 7;

    float2 acc[8][4];
#pragma unroll
    for (int i = 0; i < 8; i++)
#pragma unroll
        for (int p = 0; p < 4; p++) acc[i][p] = make_float2(0.f, 0.f);

    for (int kc = 0; kc < K; kc += 32) {
#pragma unroll
        for (int m = 0; m < 16; m++) {
            int lin = m * 256 + t;
            int row = lin >> 5, col = lin & 31;
            sA[col * 129 + row] = A[(long)(m0 + row) * lda + kc + col];
        }
#pragma unroll
        for (int m = 0; m < 16; m++) {
            int lin = m * 256 + t;
            int row = lin >> 7, col = lin & 127;
            sB[row * 128 + col] = B[(long)(kc + row) * N + n0 + col];
        }
        __syncthreads();
#pragma unroll
        for (int kk = 0; kk < 32; kk++) {
            float a[8];
#pragma unroll
            for (int i = 0; i < 8; i++) a[i] = sA[kk * 129 + ty + 16 * i];
            float2 bp[4];
#pragma unroll
            for (int p = 0; p < 4; p++) {
                bp[p].x = sB[kk * 128 + tx + 32 * p];
                bp[p].y = sB[kk * 128 + tx + 32 * p + 16];
            }
#pragma unroll
            for (int i = 0; i < 8; i++) {
                float2 ap = make_float2(a[i], a[i]);
#pragma unroll
                for (int p = 0; p < 4; p++) acc[i][p] = ffma2(ap, bp[p], acc[i][p]);
            }
        }
        __syncthreads();
    }

#pragma unroll
    for (int i = 0; i < 8; i++) {
        int r = m0 + ty + 16 * i;
#pragma unroll
        for (int p = 0; p < 4; p++) {
            long i0 = (long)r * N + n0 + tx + 32 * p;
            long i1 = i0 + 16;
            float v0 = acc[i][p].x, v1 = acc[i][p].y;
            if (Cin) { v0 += Cin[i0]; v1 += Cin[i1]; }
            Out[i0] = v0; Out[i1] = v1;
        }
    }
}

// ---------------- launcher --------------------------------------------------
extern "C" void kernel_launch(void* const* d_in, const int* in_sizes, int n_in,
                              void* d_out, int out_size)
{
    const float* elec = (const float*)d_in[0];
    const float* nuc  = (const float*)d_in[1];
    const float *dist[3], *w1[3], *b1[3], *w2[3], *g[3];

    bool dictOrder = (in_sizes[3] == DF * MID);
    if (dictOrder) {
        const int base[3] = {2, 7, 12};
        for (int tI = 0; tI < 3; tI++) {
            dist[tI] = (const float*)d_in[base[tI] + 0];
            w1[tI]   = (const float*)d_in[base[tI] + 1];
            b1[tI]   = (const float*)d_in[base[tI] + 2];
            w2[tI]   = (const float*)d_in[base[tI] + 3];
            g[tI]    = (const float*)d_in[base[tI] + 4];
        }
    } else {
        for (int tI = 0; tI < 3; tI++) {
            dist[tI] = (const float*)d_in[2 + tI];
            w1[tI]   = (const float*)d_in[5 + 3 * tI];
            b1[tI]   = (const float*)d_in[6 + 3 * tI];
            w2[tI]   = (const float*)d_in[7 + 3 * tI];
            g[tI]    = (const float*)d_in[14 + tI];
        }
    }
    const float* h_w     = (const float*)d_in[17];
    const int*   send[3] = {(const int*)d_in[18], (const int*)d_in[19], (const int*)d_in[20]};
    const int*   recv[3] = {(const int*)d_in[21], (const int*)d_in[22], (const int*)d_in[23]};
    const int    E = in_sizes[2] / DF;

    float *HX, *Z, *Gcat, *W1T, *W2T;
    cudaGetSymbolAddress((void**)&HX,   g_HX);
    cudaGetSymbolAddress((void**)&Z,    g_Z);
    cudaGetSymbolAddress((void**)&Gcat, g_Gcat);
    cudaGetSymbolAddress((void**)&W1T,  g_w1T);
    cudaGetSymbolAddress((void**)&W2T,  g_w2T);

    cudaFuncSetAttribute(edge_mma, cudaFuncAttributeMaxDynamicSharedMemorySize, SMEM_EDGE);

    cudaMemsetAsync(Z, 0, sizeof(float) * N_ELEC * 3 * KER);
    for (int tI = 0; tI < 3; tI++)
        cudaMemcpyAsync(Gcat + tI * KER * EMB, g[tI], sizeof(float) * KER * EMB,
                        cudaMemcpyDeviceToDevice);

    prep_weights<<<3, 256>>>(w1[0], w1[1], w1[2], w2[0], w2[1], w2[2]);

    // HX = electrons @ h_w   [8192,256]
    {
        dim3 grid(KER / 128, N_ELEC / 128);
        sgemm128<<<grid, 256>>>(elec, EMB, h_w, nullptr, HX, KER, EMB);
    }

    // fused tensor-core (mma.sync tf32) edge kernels, 3 types
    for (int tI = 0; tI < 3; tI++) {
        const float* hxsrc = (tI == 2) ? nuc : HX;
        edge_mma<<<E / 128, 256, SMEM_EDGE>>>(dist[tI], b1[tI],
                                              W1T + tI * 128 * 72,
                                              W2T + tI * 2 * 128 * 136,
                                              hxsrc, send[tI], recv[tI], Z, tI * KER);
    }

    // out = electrons + Z @ Gcat   [8192,256]
    {
        dim3 grid(EMB / 128, N_ELEC / 128);
        sgemm128<<<grid, 256>>>(Z, 3 * KER, Gcat, elec, (float*)d_out, EMB, 3 * KER);
    }
}

// round 5
// speedup vs baseline: 1.6424x; 1.1613x over previous
#include <cuda_runtime.h>
#include <math.h>
#include <stdint.h>

#define N_ELEC 8192
#define N_NUC  512
#define EMB    256
#define KER    256
#define DF     64
#define MID    128

// ---------------- scratch (device globals; no allocations allowed) ----------
__device__ __align__(16) float g_HX[N_ELEC * KER];       // electrons @ h_w
__device__ __align__(16) float g_Z[N_ELEC * 3 * KER];    // scatter accumulators
__device__ __align__(16) float g_Gcat[3 * KER * EMB];    // [g_same; g_anti; g_n]
// pre-transposed, k-pair-permuted, tf32-rounded weight images
__device__ __align__(16) float g_w1T[3][128 * 72];            // stride 72
__device__ __align__(16) float g_w2T[3][2][128 * 136];        // stride 136, 2 N-halves

// ---------------- helpers ---------------------------------------------------
__device__ __forceinline__ uint32_t tf32r(float x) {
    uint32_t u;
    asm("cvt.rna.tf32.f32 %0, %1;" : "=r"(u) : "f"(x));
    return u;
}
__device__ __forceinline__ float tf32f(float x) { return __uint_as_float(tf32r(x)); }

// k-pair permutation: storage position of true k within each 8-group so that
// positions (2c, 2c+1) hold true k = (c, c+4)  -> LDS.64 A/B fragment loads
__device__ __host__ __forceinline__ int kperm(int k) {
    return (k & ~7) | (((k & 3) << 1) | ((k >> 2) & 1));
}

__device__ __forceinline__ void mma_tf32(float acc[4], uint32_t a0, uint32_t a1,
                                         uint32_t a2, uint32_t a3,
                                         uint32_t b0, uint32_t b1) {
    asm volatile(
        "mma.sync.aligned.m16n8k8.row.col.f32.tf32.tf32.f32 "
        "{%0,%1,%2,%3}, {%4,%5,%6,%7}, {%8,%9}, {%0,%1,%2,%3};"
        : "+f"(acc[0]), "+f"(acc[1]), "+f"(acc[2]), "+f"(acc[3])
        : "r"(a0), "r"(a1), "r"(a2), "r"(a3), "r"(b0), "r"(b1));
}
__device__ __forceinline__ void red2(float* p, float x, float y) {
    asm volatile("red.global.add.v2.f32 [%0], {%1, %2};" :: "l"(p), "f"(x), "f"(y) : "memory");
}

__device__ __forceinline__ float2 ffma2(float2 a, float2 b, float2 c) {
    union U { float2 f; unsigned long long u; };
    U A, B, C, D; A.f = a; B.f = b; C.f = c;
    asm("fma.rn.f32x2 %0, %1, %2, %3;" : "=l"(D.u) : "l"(A.u), "l"(B.u), "l"(C.u));
    return D.f;
}
__device__ __forceinline__ float sspf(float x) {
    float sp = (x > 0.f) ? (x + log1pf(expf(-x))) : log1pf(expf(x));
    return sp - 0.69314718055994531f;
}

// ================= weight prep: transpose + permute + tf32 ==================
__global__ void prep_weights(const float* __restrict__ w1_0, const float* __restrict__ w1_1,
                             const float* __restrict__ w1_2,
                             const float* __restrict__ w2_0, const float* __restrict__ w2_1,
                             const float* __restrict__ w2_2)
{
    int ty = blockIdx.x;
    const float* w1 = (ty == 0) ? w1_0 : (ty == 1) ? w1_1 : w1_2;
    const float* w2 = (ty == 0) ? w2_0 : (ty == 1) ? w2_1 : w2_2;
    for (int i = threadIdx.x; i < 128 * 64; i += blockDim.x) {
        int n = i >> 6, k = i & 63;
        g_w1T[ty][n * 72 + kperm(k)] = tf32f(w1[k * 128 + n]);
    }
    for (int i = threadIdx.x; i < 256 * 128; i += blockDim.x) {
        int n = i >> 7, k = i & 127;
        int h = n >> 7, nn = n & 127;
        g_w2T[ty][h][nn * 136 + kperm(k)] = tf32f(w2[k * 256 + n]);
    }
}

// ================= fused mma.sync tf32 edge kernel (2 CTAs/SM) ==============
// smem:
//   header 1536B:  b1[128] @0,  send[128] @512,  recv[128] @1024
//   SM_A 1536:  phase1: dist [128][72] (36864) + w1T [128][72] @38400 (36864)
//               phase2: mid  [128][136] (69632)  -- overlays phase1 region
//   SM_W2Q 75264: streamed w2 quarter [64][136] (34816)
// total 110080 B -> 2 CTAs/SM
#define SM_B1    0
#define SM_SEND  512
#define SM_RECV  1024
#define SM_A     1536
#define SM_DIST  1536
#define SM_W1T   38400
#define SM_MID   1536
#define SM_W2Q   75264
#define SMEM_EDGE 110080

__global__ void __launch_bounds__(256, 2)
edge_mma(const float* __restrict__ dist,
         const float* __restrict__ b1,
         const float* __restrict__ w1T,       // [128*72]
         const float* __restrict__ w2T,       // [2][128*136]
         const float* __restrict__ hxsrc,     // HX [8192,256] or nuclei [512,256]
         const int*   __restrict__ senders,
         const int*   __restrict__ receivers,
         float* __restrict__ Z, int zoff)
{
    extern __shared__ char smem[];
    float* smF = (float*)smem;
    const int t = threadIdx.x, warp = t >> 5, lane = t & 31;
    const int g = lane >> 2, c = lane & 3;
    const int r0 = warp * 16;
    const long e0 = (long)blockIdx.x * 128;

    // ---- fill phase: header, w1T, dist (tf32+permute), prefetch w2 quarter 0
    if (t < 128) {
        smF[(SM_B1 >> 2) + t] = b1[t];
        ((int*)smem)[(SM_SEND >> 2) + t] = senders[e0 + t];
        ((int*)smem)[(SM_RECV >> 2) + t] = receivers[e0 + t];
    }
    {
        const float4* s1 = (const float4*)w1T;
        float4* d1 = (float4*)(smem + SM_W1T);
#pragma unroll
        for (int i = 0; i < 9; i++) d1[t + 256 * i] = s1[t + 256 * i];

        const float4* sq = (const float4*)w2T;           // quarter 0 = h0, rows 0..63
        float4* dq = (float4*)(smem + SM_W2Q);
        for (int i = t; i < 2176; i += 256) dq[i] = sq[i];

        int row = t >> 1, half32 = t & 1;
        const float4* dr = (const float4*)(dist + (e0 + row) * DF);
        float* dst = smF + (SM_DIST >> 2) + row * 72;
#pragma unroll
        for (int j = 0; j < 8; j++) {
            int c4 = half32 * 8 + j;
            float4 v = dr[c4];
            int k = c4 * 4;
            dst[kperm(k + 0)] = tf32f(v.x);
            dst[kperm(k + 1)] = tf32f(v.y);
            dst[kperm(k + 2)] = tf32f(v.z);
            dst[kperm(k + 3)] = tf32f(v.w);
        }
    }
    __syncthreads();

    // ---- stage 1: acc1 = dist @ w1  (per warp: rows r0..r0+15, 128 cols)
    float acc1[16][4];
#pragma unroll
    for (int nt = 0; nt < 16; nt++)
#pragma unroll
        for (int q = 0; q < 4; q++) acc1[nt][q] = 0.f;
    {
        const float* smD = smF + (SM_DIST >> 2);
        const float* smB = smF + (SM_W1T >> 2);
#pragma unroll
        for (int s = 0; s < 8; s++) {
            int kq = 8 * s + 2 * c;
            float2 aA = *(const float2*)(smD + (r0 + g) * 72 + kq);
            float2 aB = *(const float2*)(smD + (r0 + g + 8) * 72 + kq);
            uint32_t a0 = __float_as_uint(aA.x), a2 = __float_as_uint(aA.y);
            uint32_t a1 = __float_as_uint(aB.x), a3 = __float_as_uint(aB.y);
#pragma unroll
            for (int nt = 0; nt < 16; nt++) {
                float2 bb = *(const float2*)(smB + (nt * 8 + g) * 72 + kq);
                mma_tf32(acc1[nt], a0, a1, a2, a3,
                         __float_as_uint(bb.x), __float_as_uint(bb.y));
            }
        }
    }
    __syncthreads();   // dist/w1T region now dead

    // ---- bias + SSP -> mid tile overlaid on region A (stride 136, permuted)
    {
        float* smM = smF + (SM_MID >> 2);
        const float* sB1 = smF + (SM_B1 >> 2);
        int ra = r0 + g, rb = r0 + g + 8;
        int p0 = ((2 * c) & 3) * 2 + (((2 * c) >> 2) & 1);
        int p1 = ((2 * c + 1) & 3) * 2 + (((2 * c + 1) >> 2) & 1);
#pragma unroll
        for (int nt = 0; nt < 16; nt++) {
            int col = nt * 8 + 2 * c;
            float bb0 = sB1[col], bb1 = sB1[col + 1];
            smM[ra * 136 + nt * 8 + p0] = tf32f(sspf(acc1[nt][0] + bb0));
            smM[ra * 136 + nt * 8 + p1] = tf32f(sspf(acc1[nt][1] + bb1));
            smM[rb * 136 + nt * 8 + p0] = tf32f(sspf(acc1[nt][2] + bb0));
            smM[rb * 136 + nt * 8 + p1] = tf32f(sspf(acc1[nt][3] + bb1));
        }
    }
    __syncthreads();   // mid visible; quarter 0 (prefetched) also covered

    // ---- stage 2: 4 quarters of 64 w2 rows; epilogue red per quarter ----
    const int ra = r0 + g, rb = r0 + g + 8;
    const int sa = ((int*)smem)[(SM_SEND >> 2) + ra];
    const int sb = ((int*)smem)[(SM_SEND >> 2) + rb];
    const int qa = ((int*)smem)[(SM_RECV >> 2) + ra];
    const int qb = ((int*)smem)[(SM_RECV >> 2) + rb];
    const float* hxa = hxsrc + (long)sa * KER;
    const float* hxb = hxsrc + (long)sb * KER;
    float* Za = Z + (long)qa * (3 * KER) + zoff;
    float* Zb = Z + (long)qb * (3 * KER) + zoff;
    const float* smM = smF + (SM_MID >> 2);
    const float* smQ = smF + (SM_W2Q >> 2);

#pragma unroll
    for (int q = 0; q < 4; q++) {
        if (q > 0) {
            __syncthreads();   // previous quarter fully consumed
            const float4* sq = (const float4*)(w2T + (long)q * 64 * 136);
            float4* dq = (float4*)(smem + SM_W2Q);
            for (int i = t; i < 2176; i += 256) dq[i] = sq[i];
            __syncthreads();   // quarter q visible
        }
        float acc2[8][4];
#pragma unroll
        for (int nt = 0; nt < 8; nt++)
#pragma unroll
            for (int p = 0; p < 4; p++) acc2[nt][p] = 0.f;

#pragma unroll 4
        for (int s = 0; s < 16; s++) {
            int kq = 8 * s + 2 * c;
            float2 aA = *(const float2*)(smM + ra * 136 + kq);
            float2 aB = *(const float2*)(smM + rb * 136 + kq);
            uint32_t a0 = __float_as_uint(aA.x), a2 = __float_as_uint(aA.y);
            uint32_t a1 = __float_as_uint(aB.x), a3 = __float_as_uint(aB.y);
#pragma unroll
            for (int nt = 0; nt < 8; nt++) {
                float2 bb = *(const float2*)(smQ + (nt * 8 + g) * 136 + kq);
                mma_tf32(acc2[nt], a0, a1, a2, a3,
                         __float_as_uint(bb.x), __float_as_uint(bb.y));
            }
        }
        // epilogue: weh = we * hx[sender]; v2 red to Z[receiver]
#pragma unroll
        for (int nt = 0; nt < 8; nt++) {
            int col = q * 64 + nt * 8 + 2 * c;
            float2 ha = *(const float2*)(hxa + col);
            red2(Za + col, acc2[nt][0] * ha.x, acc2[nt][1] * ha.y);
            float2 hb = *(const float2*)(hxb + col);
            red2(Zb + col, acc2[nt][2] * hb.x, acc2[nt][3] * hb.y);
        }
    }
}

// ---------------- generic 128x128 tiled fp32 SGEMM (unchanged, passing) -----
__global__ void __launch_bounds__(256, 1)
sgemm128(const float* __restrict__ A, int lda,
         const float* __restrict__ B,
         const float* __restrict__ Cin,
         float* __restrict__ Out,
         int N, int K)
{
    __shared__ float sA[32 * 129];
    __shared__ float sB[32 * 128];
    const int t  = threadIdx.x;
    const int ty = t >> 4, tx = t & 15;
    const int m0 = blockIdx.y << 7, n0 = blockIdx.x << 7;

    float2 acc[8][4];
#pragma unroll
    for (int i = 0; i < 8; i++)
#pragma unroll
        for (int p = 0; p < 4; p++) acc[i][p] = make_float2(0.f, 0.f);

    for (int kc = 0; kc < K; kc += 32) {
#pragma unroll
        for (int m = 0; m < 16; m++) {
            int lin = m * 256 + t;
            int row = lin >> 5, col = lin & 31;
            sA[col * 129 + row] = A[(long)(m0 + row) * lda + kc + col];
        }
#pragma unroll
        for (int m = 0; m < 16; m++) {
            int lin = m * 256 + t;
            int row = lin >> 7, col = lin & 127;
            sB[row * 128 + col] = B[(long)(kc + row) * N + n0 + col];
        }
        __syncthreads();
#pragma unroll
        for (int kk = 0; kk < 32; kk++) {
            float a[8];
#pragma unroll
            for (int i = 0; i < 8; i++) a[i] = sA[kk * 129 + ty + 16 * i];
            float2 bp[4];
#pragma unroll
            for (int p = 0; p < 4; p++) {
                bp[p].x = sB[kk * 128 + tx + 32 * p];
                bp[p].y = sB[kk * 128 + tx + 32 * p + 16];
            }
#pragma unroll
            for (int i = 0; i < 8; i++) {
                float2 ap = make_float2(a[i], a[i]);
#pragma unroll
                for (int p = 0; p < 4; p++) acc[i][p] = ffma2(ap, bp[p], acc[i][p]);
            }
        }
        __syncthreads();
    }

#pragma unroll
    for (int i = 0; i < 8; i++) {
        int r = m0 + ty + 16 * i;
#pragma unroll
        for (int p = 0; p < 4; p++) {
            long i0 = (long)r * N + n0 + tx + 32 * p;
            long i1 = i0 + 16;
            float v0 = acc[i][p].x, v1 = acc[i][p].y;
            if (Cin) { v0 += Cin[i0]; v1 += Cin[i1]; }
            Out[i0] = v0; Out[i1] = v1;
        }
    }
}

// ---------------- launcher --------------------------------------------------
extern "C" void kernel_launch(void* const* d_in, const int* in_sizes, int n_in,
                              void* d_out, int out_size)
{
    const float* elec = (const float*)d_in[0];
    const float* nuc  = (const float*)d_in[1];
    const float *dist[3], *w1[3], *b1[3], *w2[3], *g[3];

    bool dictOrder = (in_sizes[3] == DF * MID);
    if (dictOrder) {
        const int base[3] = {2, 7, 12};
        for (int tI = 0; tI < 3; tI++) {
            dist[tI] = (const float*)d_in[base[tI] + 0];
            w1[tI]   = (const float*)d_in[base[tI] + 1];
            b1[tI]   = (const float*)d_in[base[tI] + 2];
            w2[tI]   = (const float*)d_in[base[tI] + 3];
            g[tI]    = (const float*)d_in[base[tI] + 4];
        }
    } else {
        for (int tI = 0; tI < 3; tI++) {
            dist[tI] = (const float*)d_in[2 + tI];
            w1[tI]   = (const float*)d_in[5 + 3 * tI];
            b1[tI]   = (const float*)d_in[6 + 3 * tI];
            w2[tI]   = (const float*)d_in[7 + 3 * tI];
            g[tI]    = (const float*)d_in[14 + tI];
        }
    }
    const float* h_w     = (const float*)d_in[17];
    const int*   send[3] = {(const int*)d_in[18], (const int*)d_in[19], (const int*)d_in[20]};
    const int*   recv[3] = {(const int*)d_in[21], (const int*)d_in[22], (const int*)d_in[23]};
    const int    E = in_sizes[2] / DF;

    float *HX, *Z, *Gcat, *W1T, *W2T;
    cudaGetSymbolAddress((void**)&HX,   g_HX);
    cudaGetSymbolAddress((void**)&Z,    g_Z);
    cudaGetSymbolAddress((void**)&Gcat, g_Gcat);
    cudaGetSymbolAddress((void**)&W1T,  g_w1T);
    cudaGetSymbolAddress((void**)&W2T,  g_w2T);

    cudaFuncSetAttribute(edge_mma, cudaFuncAttributeMaxDynamicSharedMemorySize, SMEM_EDGE);

    cudaMemsetAsync(Z, 0, sizeof(float) * N_ELEC * 3 * KER);
    for (int tI = 0; tI < 3; tI++)
        cudaMemcpyAsync(Gcat + tI * KER * EMB, g[tI], sizeof(float) * KER * EMB,
                        cudaMemcpyDeviceToDevice);

    prep_weights<<<3, 256>>>(w1[0], w1[1], w1[2], w2[0], w2[1], w2[2]);

    // HX = electrons @ h_w   [8192,256]
    {
        dim3 grid(KER / 128, N_ELEC / 128);
        sgemm128<<<grid, 256>>>(elec, EMB, h_w, nullptr, HX, KER, EMB);
    }

    // fused tensor-core (mma.sync tf32) edge kernels, 3 types
    for (int tI = 0; tI < 3; tI++) {
        const float* hxsrc = (tI == 2) ? nuc : HX;
        edge_mma<<<E / 128, 256, SMEM_EDGE>>>(dist[tI], b1[tI],
                                              W1T + tI * 128 * 72,
                                              W2T + tI * 2 * 128 * 136,
                                              hxsrc, send[tI], recv[tI], Z, tI * KER);
    }

    // out = electrons + Z @ Gcat   [8192,256]
    {
        dim3 grid(EMB / 128, N_ELEC / 128);
        sgemm128<<<grid, 256>>>(Z, 3 * KER, Gcat, elec, (float*)d_out, EMB, 3 * KER);
    }
}

// round 7
// speedup vs baseline: 2.6420x; 1.6087x over previous
#include <cuda_runtime.h>
#include <cuda_fp16.h>
#include <math.h>
#include <stdint.h>

#define N_ELEC 8192
#define N_NUC  512
#define EMB    256
#define KER    256
#define DF     64
#define MID    128

// ---------------- scratch (device globals; no allocations allowed) ----------
__device__ __align__(16) float  g_HX[N_ELEC * KER];
__device__ __align__(16) float  g_Z[N_ELEC * 3 * KER];
__device__ __align__(16) float  g_Gcat[3 * KER * EMB];
// fp16 weight images, n-major, k contiguous (strided rows for bank spread)
__device__ __align__(16) __half g_w1Th[3][128 * 72];    // [n=128][k stride 72]
__device__ __align__(16) __half g_w2Th[3][256 * 136];   // [n=256][k stride 136]

// ---------------- helpers ---------------------------------------------------
__device__ __forceinline__ void ldm_x4(uint32_t r[4], uint32_t saddr) {
    asm volatile("ldmatrix.sync.aligned.m8n8.x4.shared.b16 {%0,%1,%2,%3}, [%4];"
                 : "=r"(r[0]), "=r"(r[1]), "=r"(r[2]), "=r"(r[3]) : "r"(saddr));
}
__device__ __forceinline__ void mma_f16(float acc[4], const uint32_t a[4],
                                        uint32_t b0, uint32_t b1) {
    asm volatile(
        "mma.sync.aligned.m16n8k16.row.col.f32.f16.f16.f32 "
        "{%0,%1,%2,%3}, {%4,%5,%6,%7}, {%8,%9}, {%0,%1,%2,%3};"
        : "+f"(acc[0]), "+f"(acc[1]), "+f"(acc[2]), "+f"(acc[3])
        : "r"(a[0]), "r"(a[1]), "r"(a[2]), "r"(a[3]), "r"(b0), "r"(b1));
}
__device__ __forceinline__ void red2(float* p, float x, float y) {
    asm volatile("red.global.add.v2.f32 [%0], {%1, %2};" :: "l"(p), "f"(x), "f"(y) : "memory");
}
__device__ __forceinline__ void cp16(uint32_t saddr, const void* g) {
    asm volatile("cp.async.cg.shared.global [%0], [%1], 16;" :: "r"(saddr), "l"(g));
}
#define CP_COMMIT() asm volatile("cp.async.commit_group;" ::: "memory")
#define CP_WAIT(n)  asm volatile("cp.async.wait_group %0;" :: "n"(n) : "memory")

__device__ __forceinline__ uint32_t smem_u32(const void* p) {
    uint32_t a;
    asm("{ .reg .u64 t; cvta.to.shared.u64 t, %1; cvt.u32.u64 %0, t; }" : "=r"(a) : "l"(p));
    return a;
}
// pack two f32 into f16x2: lo = x, hi = y
__device__ __forceinline__ uint32_t packh2(float x, float y) {
    uint32_t r;
    asm("cvt.rn.f16x2.f32 %0, %1, %2;" : "=r"(r) : "f"(y), "f"(x));
    return r;
}
__device__ __forceinline__ float2 ffma2(float2 a, float2 b, float2 c) {
    union U { float2 f; unsigned long long u; };
    U A, B, C, D; A.f = a; B.f = b; C.f = c;
    asm("fma.rn.f32x2 %0, %1, %2, %3;" : "=l"(D.u) : "l"(A.u), "l"(B.u), "l"(C.u));
    return D.f;
}
__device__ __forceinline__ float sspf(float x) {
    float sp = (x > 0.f) ? (x + log1pf(expf(-x))) : log1pf(expf(x));
    return sp - 0.69314718055994531f;
}

// ================= weight prep: transpose + fp16 ============================
__global__ void prep_weights(const float* __restrict__ w1_0, const float* __restrict__ w1_1,
                             const float* __restrict__ w1_2,
                             const float* __restrict__ w2_0, const float* __restrict__ w2_1,
                             const float* __restrict__ w2_2)
{
    int ty = blockIdx.x;
    const float* w1 = (ty == 0) ? w1_0 : (ty == 1) ? w1_1 : w1_2;
    const float* w2 = (ty == 0) ? w2_0 : (ty == 1) ? w2_1 : w2_2;
    for (int i = threadIdx.x; i < 128 * 64; i += blockDim.x) {
        int n = i >> 6, k = i & 63;
        g_w1Th[ty][n * 72 + k] = __float2half(w1[k * 128 + n]);
    }
    for (int i = threadIdx.x; i < 256 * 128; i += blockDim.x) {
        int n = i >> 7, k = i & 127;
        g_w2Th[ty][n * 136 + k] = __float2half(w2[k * 256 + n]);
    }
}

// ================= fused fp16 mma edge kernel (all 3 types, 3 CTAs/SM) ======
// smem bytes:
//   0:     b1[128] f32 (512)   512: send[128] (512)   1024: recv[128] (512)
//   1536:  dist half [128][72]  (18432) -> 19968
//   19968: w1T  half [128][72]  (18432) -> 38400
//   38400: w2 quarter buf A half [64][136] (17408) -> 55808
//   55808: w2 quarter buf B (17408) -> 73216       total 73216 -> 3 CTAs/SM
#define SH_B1    0
#define SH_SEND  512
#define SH_RECV  1024
#define SH_DIST  1536
#define SH_W1T   19968
#define SH_W2A   38400
#define SH_W2B   55808
#define SMEM_EDGE 73216

__global__ void __launch_bounds__(256, 3)
edge_fused(const float* __restrict__ dist0, const float* __restrict__ dist1,
           const float* __restrict__ dist2,
           const float* __restrict__ b1_0, const float* __restrict__ b1_1,
           const float* __restrict__ b1_2,
           const float* __restrict__ HX, const float* __restrict__ nuc,
           const int* __restrict__ s0, const int* __restrict__ s1, const int* __restrict__ s2,
           const int* __restrict__ r0p, const int* __restrict__ r1p, const int* __restrict__ r2p,
           float* __restrict__ Z, int nblk)
{
    extern __shared__ char smem[];
    float* smF = (float*)smem;
    const uint32_t sbase = smem_u32(smem);
    const int t = threadIdx.x, warp = t >> 5, lane = t & 31;
    const int g = lane >> 2, c = lane & 3;
    const int wr0 = warp * 16;

    const int ty  = blockIdx.x / nblk;
    const int blk = blockIdx.x - ty * nblk;
    const float* dist  = (ty == 0) ? dist0 : (ty == 1) ? dist1 : dist2;
    const float* b1    = (ty == 0) ? b1_0  : (ty == 1) ? b1_1  : b1_2;
    const int*   snd   = (ty == 0) ? s0 : (ty == 1) ? s1 : s2;
    const int*   rcv   = (ty == 0) ? r0p : (ty == 1) ? r1p : r2p;
    const float* hxsrc = (ty == 2) ? nuc : HX;
    const int    zoff  = ty * KER;
    const long   e0    = (long)blk * 128;
    const __half* w1T  = g_w1Th[ty];
    const __half* w2T  = g_w2Th[ty];

    // ---- fill: header + dist(f32->half) + async w1T + async w2 quarter 0 ----
    if (t < 128) {
        smF[(SH_B1 >> 2) + t] = b1[t];
        ((int*)smem)[(SH_SEND >> 2) + t] = snd[e0 + t];
        ((int*)smem)[(SH_RECV >> 2) + t] = rcv[e0 + t];
    }
    {
        int row = t >> 1, part = t & 1;
        const float4* dr = (const float4*)(dist + (e0 + row) * DF);
        char* dst = smem + SH_DIST + row * 144;
#pragma unroll
        for (int j = 0; j < 8; j++) {
            int c4 = part * 8 + j;
            float4 v = dr[c4];
            uint2 h;
            h.x = packh2(v.x, v.y);
            h.y = packh2(v.z, v.w);
            *(uint2*)(dst + c4 * 8) = h;
        }
    }
    // w1T: 18432B = 1152 x16B (group 0)
    for (int i = t; i < 1152; i += 256)
        cp16(sbase + SH_W1T + i * 16, (const char*)w1T + i * 16);
    CP_COMMIT();
    // w2 quarter 0: 17408B = 1088 x16B (group 1)
    for (int i = t; i < 1088; i += 256)
        cp16(sbase + SH_W2A + i * 16, (const char*)w2T + i * 16);
    CP_COMMIT();

    CP_WAIT(1);          // w1T landed (q0 may still be in flight)
    __syncthreads();     // dist/header/w1T visible to all

    // per-lane ldmatrix address components
    const int lrowA = (lane & 7) + ((lane >> 3) & 1) * 8;   // A: row within 16-block
    const int lkA   = (lane >> 4) * 8;                       // A: k offset 0/8
    const int lrowB = ((lane >> 4) << 3) + (lane & 7);       // B: row within 16 (nt pair)
    const int lkB   = ((lane >> 3) & 1) * 8;                 // B: k offset 0/8
    const uint32_t aBase  = sbase + SH_DIST + (wr0 + lrowA) * 144 + lkA * 2;
    const uint32_t b1Base = sbase + SH_W1T + lrowB * 144 + lkB * 2;

    // ---- stage 1 (two n-passes), SSP in regs -> stage-2 A fragments mreg ----
    uint32_t mreg[8][4];
#pragma unroll
    for (int pass = 0; pass < 2; pass++) {
        float acc[8][4];
#pragma unroll
        for (int j = 0; j < 8; j++)
#pragma unroll
            for (int q = 0; q < 4; q++) acc[j][q] = 0.f;
#pragma unroll
        for (int s = 0; s < 4; s++) {            // K = 64 -> 4 steps of 16
            uint32_t a[4];
            ldm_x4(a, aBase + s * 32);
#pragma unroll
            for (int p = 0; p < 4; p++) {        // 4 nt-pairs per pass
                uint32_t b[4];
                ldm_x4(b, b1Base + (pass * 4 + p) * 16 * 144 + s * 32);
                mma_f16(acc[2 * p],     a, b[0], b[1]);
                mma_f16(acc[2 * p + 1], a, b[2], b[3]);
            }
        }
        const float* sB1 = smF + (SH_B1 >> 2);
#pragma unroll
        for (int p = 0; p < 4; p++) {
            int nt0 = pass * 8 + 2 * p, nt1 = nt0 + 1;
            float bA0 = sB1[nt0 * 8 + 2 * c], bA1 = sB1[nt0 * 8 + 2 * c + 1];
            float bB0 = sB1[nt1 * 8 + 2 * c], bB1 = sB1[nt1 * 8 + 2 * c + 1];
            int s2i = pass * 4 + p;
            mreg[s2i][0] = packh2(sspf(acc[2*p][0] + bA0),   sspf(acc[2*p][1] + bA1));
            mreg[s2i][1] = packh2(sspf(acc[2*p][2] + bA0),   sspf(acc[2*p][3] + bA1));
            mreg[s2i][2] = packh2(sspf(acc[2*p+1][0] + bB0), sspf(acc[2*p+1][1] + bB1));
            mreg[s2i][3] = packh2(sspf(acc[2*p+1][2] + bB0), sspf(acc[2*p+1][3] + bB1));
        }
    }

    // ---- epilogue pointers ----
    const int ra = wr0 + g, rb = wr0 + g + 8;
    const int sa = ((int*)smem)[(SH_SEND >> 2) + ra];
    const int sb = ((int*)smem)[(SH_SEND >> 2) + rb];
    const int qa = ((int*)smem)[(SH_RECV >> 2) + ra];
    const int qb = ((int*)smem)[(SH_RECV >> 2) + rb];
    const float* hxa = hxsrc + (long)sa * KER;
    const float* hxb = hxsrc + (long)sb * KER;
    float* Za = Z + (long)qa * (3 * KER) + zoff;
    float* Zb = Z + (long)qb * (3 * KER) + zoff;

    CP_WAIT(0);          // quarter 0 landed
    __syncthreads();

    // ---- stage 2: 4 w2 quarters (64 n-cols each), double-buffered ----
#pragma unroll
    for (int q = 0; q < 4; q++) {
        if (q < 3) {     // prefetch next quarter into other buffer
            uint32_t dstq = sbase + (((q + 1) & 1) ? SH_W2B : SH_W2A);
            const char* srcq = (const char*)(w2T + (long)(q + 1) * 64 * 136);
            for (int i = t; i < 1088; i += 256) cp16(dstq + i * 16, srcq + i * 16);
            CP_COMMIT();
        }
        const uint32_t swq = sbase + ((q & 1) ? SH_W2B : SH_W2A);
        const uint32_t b2Base = swq + lrowB * 272 + lkB * 2;
#pragma unroll
        for (int h = 0; h < 2; h++) {            // 2 halves of 32 n-cols
            float acc2[4][4];
#pragma unroll
            for (int j = 0; j < 4; j++)
#pragma unroll
                for (int p = 0; p < 4; p++) acc2[j][p] = 0.f;
#pragma unroll
            for (int s = 0; s < 8; s++) {        // K = 128 -> 8 steps
#pragma unroll
                for (int p = 0; p < 2; p++) {    // 2 nt-pairs per half
                    uint32_t b[4];
                    ldm_x4(b, b2Base + (h * 2 + p) * 16 * 272 + s * 32);
                    mma_f16(acc2[2 * p],     mreg[s], b[0], b[1]);
                    mma_f16(acc2[2 * p + 1], mreg[s], b[2], b[3]);
                }
            }
            // epilogue: weh = we * hx[sender]; v2 red to Z[receiver]
#pragma unroll
            for (int j = 0; j < 4; j++) {
                int col = q * 64 + h * 32 + j * 8 + 2 * c;
                float2 ha = *(const float2*)(hxa + col);
                red2(Za + col, acc2[j][0] * ha.x, acc2[j][1] * ha.y);
                float2 hb = *(const float2*)(hxb + col);
                red2(Zb + col, acc2[j][2] * hb.x, acc2[j][3] * hb.y);
            }
        }
        CP_WAIT(0);
        __syncthreads();
    }
}

// ---------------- generic 128x128 tiled fp32 SGEMM (unchanged, passing) -----
__global__ void __launch_bounds__(256, 1)
sgemm128(const float* __restrict__ A, int lda,
         const float* __restrict__ B,
         const float* __restrict__ Cin,
         float* __restrict__ Out,
         int N, int K)
{
    __shared__ float sA[32 * 129];
    __shared__ float sB[32 * 128];
    const int t  = threadIdx.x;
    const int ty = t >> 4, tx = t & 15;
    const int m0 = blockIdx.y << 7, n0 = blockIdx.x << 7;

    float2 acc[8][4];
#pragma unroll
    for (int i = 0; i < 8; i++)
#pragma unroll
        for (int p = 0; p < 4; p++) acc[i][p] = make_float2(0.f, 0.f);

    for (int kc = 0; kc < K; kc += 32) {
#pragma unroll
        for (int m = 0; m < 16; m++) {
            int lin = m * 256 + t;
            int row = lin >> 5, col = lin & 31;
            sA[col * 129 + row] = A[(long)(m0 + row) * lda + kc + col];
        }
#pragma unroll
        for (int m = 0; m < 16; m++) {
            int lin = m * 256 + t;
            int row = lin >> 7, col = lin & 127;
            sB[row * 128 + col] = B[(long)(kc + row) * N + n0 + col];
        }
        __syncthreads();
#pragma unroll
        for (int kk = 0; kk < 32; kk++) {
            float a[8];
#pragma unroll
            for (int i = 0; i < 8; i++) a[i] = sA[kk * 129 + ty + 16 * i];
            float2 bp[4];
#pragma unroll
            for (int p = 0; p < 4; p++) {
                bp[p].x = sB[kk * 128 + tx + 32 * p];
                bp[p].y = sB[kk * 128 + tx + 32 * p + 16];
            }
#pragma unroll
            for (int i = 0; i < 8; i++) {
                float2 ap = make_float2(a[i], a[i]);
#pragma unroll
                for (int p = 0; p < 4; p++) acc[i][p] = ffma2(ap, bp[p], acc[i][p]);
            }
        }
        __syncthreads();
    }

#pragma unroll
    for (int i = 0; i < 8; i++) {
        int r = m0 + ty + 16 * i;
#pragma unroll
        for (int p = 0; p < 4; p++) {
            long i0 = (long)r * N + n0 + tx + 32 * p;
            long i1 = i0 + 16;
            float v0 = acc[i][p].x, v1 = acc[i][p].y;
            if (Cin) { v0 += Cin[i0]; v1 += Cin[i1]; }
            Out[i0] = v0; Out[i1] = v1;
        }
    }
}

// ---------------- launcher --------------------------------------------------
extern "C" void kernel_launch(void* const* d_in, const int* in_sizes, int n_in,
                              void* d_out, int out_size)
{
    const float* elec = (const float*)d_in[0];
    const float* nuc  = (const float*)d_in[1];
    const float *dist[3], *w1[3], *b1[3], *w2[3], *g[3];

    bool dictOrder = (in_sizes[3] == DF * MID);
    if (dictOrder) {
        const int base[3] = {2, 7, 12};
        for (int tI = 0; tI < 3; tI++) {
            dist[tI] = (const float*)d_in[base[tI] + 0];
            w1[tI]   = (const float*)d_in[base[tI] + 1];
            b1[tI]   = (const float*)d_in[base[tI] + 2];
            w2[tI]   = (const float*)d_in[base[tI] + 3];
            g[tI]    = (const float*)d_in[base[tI] + 4];
        }
    } else {
        for (int tI = 0; tI < 3; tI++) {
            dist[tI] = (const float*)d_in[2 + tI];
            w1[tI]   = (const float*)d_in[5 + 3 * tI];
            b1[tI]   = (const float*)d_in[6 + 3 * tI];
            w2[tI]   = (const float*)d_in[7 + 3 * tI];
            g[tI]    = (const float*)d_in[14 + tI];
        }
    }
    const float* h_w     = (const float*)d_in[17];
    const int*   send[3] = {(const int*)d_in[18], (const int*)d_in[19], (const int*)d_in[20]};
    const int*   recv[3] = {(const int*)d_in[21], (const int*)d_in[22], (const int*)d_in[23]};
    const int    E = in_sizes[2] / DF;
    const int    nblk = E / 128;

    float *HX, *Z, *Gcat;
    cudaGetSymbolAddress((void**)&HX,   g_HX);
    cudaGetSymbolAddress((void**)&Z,    g_Z);
    cudaGetSymbolAddress((void**)&Gcat, g_Gcat);

    cudaFuncSetAttribute(edge_fused, cudaFuncAttributeMaxDynamicSharedMemorySize, SMEM_EDGE);

    cudaMemsetAsync(Z, 0, sizeof(float) * N_ELEC * 3 * KER);
    for (int tI = 0; tI < 3; tI++)
        cudaMemcpyAsync(Gcat + tI * KER * EMB, g[tI], sizeof(float) * KER * EMB,
                        cudaMemcpyDeviceToDevice);

    prep_weights<<<3, 256>>>(w1[0], w1[1], w1[2], w2[0], w2[1], w2[2]);

    // HX = electrons @ h_w   [8192,256]
    {
        dim3 grid(KER / 128, N_ELEC / 128);
        sgemm128<<<grid, 256>>>(elec, EMB, h_w, nullptr, HX, KER, EMB);
    }

    // fused fp16-mma edge kernel, all 3 types in one launch
    edge_fused<<<3 * nblk, 256, SMEM_EDGE>>>(dist[0], dist[1], dist[2],
                                             b1[0], b1[1], b1[2],
                                             HX, nuc,
                                             send[0], send[1], send[2],
                                             recv[0], recv[1], recv[2],
                                             Z, nblk);

    // out = electrons + Z @ Gcat   [8192,256]
    {
        dim3 grid(EMB / 128, N_ELEC / 128);
        sgemm128<<<grid, 256>>>(Z, 3 * KER, Gcat, elec, (float*)d_out, EMB, 3 * KER);
    }
}

// round 8
// speedup vs baseline: 2.8078x; 1.0627x over previous
#include <cuda_runtime.h>
#include <cuda_fp16.h>
#include <math.h>
#include <stdint.h>

#define N_ELEC 8192
#define N_NUC  512
#define EMB    256
#define KER    256
#define DF     64
#define MID    128

// ---------------- scratch (device globals; no allocations allowed) ----------
__device__ __align__(16) float  g_HX[N_ELEC * KER];
__device__ __align__(16) float  g_Z[N_ELEC * 3 * KER];
__device__ __align__(16) __half g_Zh[N_ELEC * 3 * KER];     // fp16 copy of Z
__device__ __align__(16) __half g_elech[N_ELEC * EMB];      // fp16 electrons
// fp16 weight images, n-major, k contiguous, padded row strides
__device__ __align__(16) __half g_w1Th[3][128 * 72];
__device__ __align__(16) __half g_w2Th[3][256 * 136];
__device__ __align__(16) __half g_hwh[256 * 264];           // h_w^T  [n=KER][k=EMB pad 264]
__device__ __align__(16) __half g_GTh[256 * 776];           // Gcat^T [n=EMB][k=768 pad 776]

// ---------------- helpers ---------------------------------------------------
__device__ __forceinline__ void ldm_x4(uint32_t r[4], uint32_t saddr) {
    asm volatile("ldmatrix.sync.aligned.m8n8.x4.shared.b16 {%0,%1,%2,%3}, [%4];"
                 : "=r"(r[0]), "=r"(r[1]), "=r"(r[2]), "=r"(r[3]) : "r"(saddr));
}
__device__ __forceinline__ void mma_f16(float acc[4], const uint32_t a[4],
                                        uint32_t b0, uint32_t b1) {
    asm volatile(
        "mma.sync.aligned.m16n8k16.row.col.f32.f16.f16.f32 "
        "{%0,%1,%2,%3}, {%4,%5,%6,%7}, {%8,%9}, {%0,%1,%2,%3};"
        : "+f"(acc[0]), "+f"(acc[1]), "+f"(acc[2]), "+f"(acc[3])
        : "r"(a[0]), "r"(a[1]), "r"(a[2]), "r"(a[3]), "r"(b0), "r"(b1));
}
__device__ __forceinline__ void red2(float* p, float x, float y) {
    asm volatile("red.global.add.v2.f32 [%0], {%1, %2};" :: "l"(p), "f"(x), "f"(y) : "memory");
}
__device__ __forceinline__ void cp16(uint32_t saddr, const void* g) {
    asm volatile("cp.async.cg.shared.global [%0], [%1], 16;" :: "r"(saddr), "l"(g));
}
#define CP_COMMIT() asm volatile("cp.async.commit_group;" ::: "memory")
#define CP_WAIT(n)  asm volatile("cp.async.wait_group %0;" :: "n"(n) : "memory")

__device__ __forceinline__ uint32_t smem_u32(const void* p) {
    uint32_t a;
    asm("{ .reg .u64 t; cvta.to.shared.u64 t, %1; cvt.u32.u64 %0, t; }" : "=r"(a) : "l"(p));
    return a;
}
__device__ __forceinline__ uint32_t packh2(float x, float y) {   // lo=x, hi=y
    uint32_t r;
    asm("cvt.rn.f16x2.f32 %0, %1, %2;" : "=r"(r) : "f"(y), "f"(x));
    return r;
}
__device__ __forceinline__ float sspf(float x) {
    float sp = (x > 0.f) ? (x + log1pf(expf(-x))) : log1pf(expf(x));
    return sp - 0.69314718055994531f;
}

// ================= elementwise fp32 -> fp16 =================================
__global__ void f2h(const float4* __restrict__ src, uint2* __restrict__ dst, int n4) {
    int i = blockIdx.x * blockDim.x + threadIdx.x;
    if (i < n4) {
        float4 v = src[i];
        uint2 h;
        h.x = packh2(v.x, v.y);
        h.y = packh2(v.z, v.w);
        dst[i] = h;
    }
}

// ================= weight prep: transpose + fp16 ============================
__global__ void prep_weights(const float* __restrict__ w1_0, const float* __restrict__ w1_1,
                             const float* __restrict__ w1_2,
                             const float* __restrict__ w2_0, const float* __restrict__ w2_1,
                             const float* __restrict__ w2_2,
                             const float* __restrict__ g_0, const float* __restrict__ g_1,
                             const float* __restrict__ g_2,
                             const float* __restrict__ h_w)
{
    int ty = blockIdx.x;
    const float* w1 = (ty == 0) ? w1_0 : (ty == 1) ? w1_1 : w1_2;
    const float* w2 = (ty == 0) ? w2_0 : (ty == 1) ? w2_1 : w2_2;
    const float* gg = (ty == 0) ? g_0  : (ty == 1) ? g_1  : g_2;
    for (int i = threadIdx.x; i < 128 * 64; i += blockDim.x) {
        int n = i >> 6, k = i & 63;
        g_w1Th[ty][n * 72 + k] = __float2half(w1[k * 128 + n]);
    }
    for (int i = threadIdx.x; i < 256 * 128; i += blockDim.x) {
        int n = i >> 7, k = i & 127;
        g_w2Th[ty][n * 136 + k] = __float2half(w2[k * 256 + n]);
    }
    // Gcat^T image: g[ty] is [KER=256, EMB=256]; global k = ty*256+kk, col n
    for (int i = threadIdx.x; i < 256 * 256; i += blockDim.x) {
        int n = i >> 8, kk = i & 255;
        g_GTh[n * 776 + ty * 256 + kk] = __float2half(gg[kk * 256 + n]);
    }
    // h_w^T image (block 0 only): h_w [EMB, KER]
    if (ty == 0)
        for (int i = threadIdx.x; i < 256 * 256; i += blockDim.x) {
            int n = i >> 8, k = i & 255;
            g_hwh[n * 264 + k] = __float2half(h_w[k * 256 + n]);
        }
}

// ================= fp16 tensor-core GEMM: Out[M,256] = (Cin?) + Ah @ Bh^T ===
// Ah [M][K] dense fp16; Bh [256 n][Kpad] fp16 n-major image.
// tile: BM=64 x BN=128, 8 warps = 4 row-groups x 2 col-halves, cp.async x2 buf
#define GSM_A0 0
#define GSM_A1 9216
#define GSM_B0 18432
#define GSM_B1 36864
#define GSM_TOT 55296

__global__ void __launch_bounds__(256, 3)
gemm_h(const __half* __restrict__ A, int K,
       const __half* __restrict__ B, int Kpad,
       const float* __restrict__ Cin, float* __restrict__ Out)
{
    extern __shared__ char smem[];
    const uint32_t sbase = smem_u32(smem);
    const int t = threadIdx.x, warp = t >> 5, lane = t & 31;
    const int wm = warp & 3, wn = warp >> 2;
    const int g = lane >> 2, c = lane & 3;
    const int n0 = blockIdx.x * 128, m0 = blockIdx.y * 64;
    const int nch = K / 64;

    const int lrowA = (lane & 7) + ((lane >> 3) & 1) * 8;
    const int lkA   = (lane >> 4) * 8;
    const int lrowB = ((lane >> 4) << 3) + (lane & 7);
    const int lkB   = ((lane >> 3) & 1) * 8;

    float acc[8][4];
#pragma unroll
    for (int j = 0; j < 8; j++)
#pragma unroll
        for (int p = 0; p < 4; p++) acc[j][p] = 0.f;

    // chunk loader: A 64x64 half (9216B w/ stride 144), B 128x64 half
#define LOAD_CHUNK(ch) do {                                                     \
        uint32_t abuf = sbase + (((ch) & 1) ? GSM_A1 : GSM_A0);                 \
        uint32_t bbuf = sbase + (((ch) & 1) ? GSM_B1 : GSM_B0);                 \
        const char* ag = (const char*)(A + (long)m0 * K + (ch) * 64);           \
        _Pragma("unroll")                                                       \
        for (int i = 0; i < 2; i++) {                                           \
            int idx = t + 256 * i, row = idx >> 3, cc = idx & 7;                \
            cp16(abuf + row * 144 + cc * 16, ag + (long)row * K * 2 + cc * 16); \
        }                                                                       \
        const char* bg = (const char*)(B + (long)n0 * Kpad + (ch) * 64);        \
        _Pragma("unroll")                                                       \
        for (int i = 0; i < 4; i++) {                                           \
            int idx = t + 256 * i, row = idx >> 3, cc = idx & 7;                \
            cp16(bbuf + row * 144 + cc * 16, bg + (long)row * Kpad * 2 + cc * 16); \
        }                                                                       \
        CP_COMMIT();                                                            \
    } while (0)

    LOAD_CHUNK(0);
    for (int ch = 0; ch < nch; ch++) {
        if (ch + 1 < nch) { LOAD_CHUNK(ch + 1); CP_WAIT(1); }
        else              { CP_WAIT(0); }
        __syncthreads();
        uint32_t abuf = sbase + ((ch & 1) ? GSM_A1 : GSM_A0);
        uint32_t bbuf = sbase + ((ch & 1) ? GSM_B1 : GSM_B0);
        uint32_t aB = abuf + (wm * 16 + lrowA) * 144 + lkA * 2;
        uint32_t bB = bbuf + (wn * 64 + lrowB) * 144 + lkB * 2;
#pragma unroll
        for (int s = 0; s < 4; s++) {
            uint32_t a[4];
            ldm_x4(a, aB + s * 32);
#pragma unroll
            for (int p = 0; p < 4; p++) {
                uint32_t b[4];
                ldm_x4(b, bB + p * 16 * 144 + s * 32);
                mma_f16(acc[2 * p],     a, b[0], b[1]);
                mma_f16(acc[2 * p + 1], a, b[2], b[3]);
            }
        }
        __syncthreads();
    }

    // epilogue: rows m0+wm*16+g (+8), cols n0+wn*64+j*8+2c (+1)
    int ra = m0 + wm * 16 + g, rb = ra + 8;
#pragma unroll
    for (int j = 0; j < 8; j++) {
        int col = n0 + wn * 64 + j * 8 + 2 * c;
        float2 v0 = make_float2(acc[j][0], acc[j][1]);
        float2 v1 = make_float2(acc[j][2], acc[j][3]);
        if (Cin) {
            float2 c0 = *(const float2*)(Cin + (long)ra * 256 + col);
            float2 c1 = *(const float2*)(Cin + (long)rb * 256 + col);
            v0.x += c0.x; v0.y += c0.y; v1.x += c1.x; v1.y += c1.y;
        }
        *(float2*)(Out + (long)ra * 256 + col) = v0;
        *(float2*)(Out + (long)rb * 256 + col) = v1;
    }
}

// ================= fused fp16 mma edge kernel (unchanged from R7) ===========
#define SH_B1    0
#define SH_SEND  512
#define SH_RECV  1024
#define SH_DIST  1536
#define SH_W1T   19968
#define SH_W2A   38400
#define SH_W2B   55808
#define SMEM_EDGE 73216

__global__ void __launch_bounds__(256, 3)
edge_fused(const float* __restrict__ dist0, const float* __restrict__ dist1,
           const float* __restrict__ dist2,
           const float* __restrict__ b1_0, const float* __restrict__ b1_1,
           const float* __restrict__ b1_2,
           const float* __restrict__ HX, const float* __restrict__ nuc,
           const int* __restrict__ s0, const int* __restrict__ s1, const int* __restrict__ s2,
           const int* __restrict__ r0p, const int* __restrict__ r1p, const int* __restrict__ r2p,
           float* __restrict__ Z, int nblk)
{
    extern __shared__ char smem[];
    float* smF = (float*)smem;
    const uint32_t sbase = smem_u32(smem);
    const int t = threadIdx.x, warp = t >> 5, lane = t & 31;
    const int g = lane >> 2, c = lane & 3;
    const int wr0 = warp * 16;

    const int ty  = blockIdx.x / nblk;
    const int blk = blockIdx.x - ty * nblk;
    const float* dist  = (ty == 0) ? dist0 : (ty == 1) ? dist1 : dist2;
    const float* b1    = (ty == 0) ? b1_0  : (ty == 1) ? b1_1  : b1_2;
    const int*   snd   = (ty == 0) ? s0 : (ty == 1) ? s1 : s2;
    const int*   rcv   = (ty == 0) ? r0p : (ty == 1) ? r1p : r2p;
    const float* hxsrc = (ty == 2) ? nuc : HX;
    const int    zoff  = ty * KER;
    const long   e0    = (long)blk * 128;
    const __half* w1T  = g_w1Th[ty];
    const __half* w2T  = g_w2Th[ty];

    if (t < 128) {
        smF[(SH_B1 >> 2) + t] = b1[t];
        ((int*)smem)[(SH_SEND >> 2) + t] = snd[e0 + t];
        ((int*)smem)[(SH_RECV >> 2) + t] = rcv[e0 + t];
    }
    {
        int row = t >> 1, part = t & 1;
        const float4* dr = (const float4*)(dist + (e0 + row) * DF);
        char* dst = smem + SH_DIST + row * 144;
#pragma unroll
        for (int j = 0; j < 8; j++) {
            int c4 = part * 8 + j;
            float4 v = dr[c4];
            uint2 h;
            h.x = packh2(v.x, v.y);
            h.y = packh2(v.z, v.w);
            *(uint2*)(dst + c4 * 8) = h;
        }
    }
    for (int i = t; i < 1152; i += 256)
        cp16(sbase + SH_W1T + i * 16, (const char*)w1T + i * 16);
    CP_COMMIT();
    for (int i = t; i < 1088; i += 256)
        cp16(sbase + SH_W2A + i * 16, (const char*)w2T + i * 16);
    CP_COMMIT();

    CP_WAIT(1);
    __syncthreads();

    const int lrowA = (lane & 7) + ((lane >> 3) & 1) * 8;
    const int lkA   = (lane >> 4) * 8;
    const int lrowB = ((lane >> 4) << 3) + (lane & 7);
    const int lkB   = ((lane >> 3) & 1) * 8;
    const uint32_t aBase  = sbase + SH_DIST + (wr0 + lrowA) * 144 + lkA * 2;
    const uint32_t b1Base = sbase + SH_W1T + lrowB * 144 + lkB * 2;

    uint32_t mreg[8][4];
#pragma unroll
    for (int pass = 0; pass < 2; pass++) {
        float acc[8][4];
#pragma unroll
        for (int j = 0; j < 8; j++)
#pragma unroll
            for (int q = 0; q < 4; q++) acc[j][q] = 0.f;
#pragma unroll
        for (int s = 0; s < 4; s++) {
            uint32_t a[4];
            ldm_x4(a, aBase + s * 32);
#pragma unroll
            for (int p = 0; p < 4; p++) {
                uint32_t b[4];
                ldm_x4(b, b1Base + (pass * 4 + p) * 16 * 144 + s * 32);
                mma_f16(acc[2 * p],     a, b[0], b[1]);
                mma_f16(acc[2 * p + 1], a, b[2], b[3]);
            }
        }
        const float* sB1 = smF + (SH_B1 >> 2);
#pragma unroll
        for (int p = 0; p < 4; p++) {
            int nt0 = pass * 8 + 2 * p, nt1 = nt0 + 1;
            float bA0 = sB1[nt0 * 8 + 2 * c], bA1 = sB1[nt0 * 8 + 2 * c + 1];
            float bB0 = sB1[nt1 * 8 + 2 * c], bB1 = sB1[nt1 * 8 + 2 * c + 1];
            int s2i = pass * 4 + p;
            mreg[s2i][0] = packh2(sspf(acc[2*p][0] + bA0),   sspf(acc[2*p][1] + bA1));
            mreg[s2i][1] = packh2(sspf(acc[2*p][2] + bA0),   sspf(acc[2*p][3] + bA1));
            mreg[s2i][2] = packh2(sspf(acc[2*p+1][0] + bB0), sspf(acc[2*p+1][1] + bB1));
            mreg[s2i][3] = packh2(sspf(acc[2*p+1][2] + bB0), sspf(acc[2*p+1][3] + bB1));
        }
    }

    const int ra = wr0 + g, rb = wr0 + g + 8;
    const int sa = ((int*)smem)[(SH_SEND >> 2) + ra];
    const int sb = ((int*)smem)[(SH_SEND >> 2) + rb];
    const int qa = ((int*)smem)[(SH_RECV >> 2) + ra];
    const int qb = ((int*)smem)[(SH_RECV >> 2) + rb];
    const float* hxa = hxsrc + (long)sa * KER;
    const float* hxb = hxsrc + (long)sb * KER;
    float* Za = Z + (long)qa * (3 * KER) + zoff;
    float* Zb = Z + (long)qb * (3 * KER) + zoff;

    CP_WAIT(0);
    __syncthreads();

#pragma unroll
    for (int q = 0; q < 4; q++) {
        if (q < 3) {
            uint32_t dstq = sbase + (((q + 1) & 1) ? SH_W2B : SH_W2A);
            const char* srcq = (const char*)(w2T + (long)(q + 1) * 64 * 136);
            for (int i = t; i < 1088; i += 256) cp16(dstq + i * 16, srcq + i * 16);
            CP_COMMIT();
        }
        const uint32_t swq = sbase + ((q & 1) ? SH_W2B : SH_W2A);
        const uint32_t b2Base = swq + lrowB * 272 + lkB * 2;
#pragma unroll
        for (int h = 0; h < 2; h++) {
            float acc2[4][4];
#pragma unroll
            for (int j = 0; j < 4; j++)
#pragma unroll
                for (int p = 0; p < 4; p++) acc2[j][p] = 0.f;
#pragma unroll
            for (int s = 0; s < 8; s++) {
#pragma unroll
                for (int p = 0; p < 2; p++) {
                    uint32_t b[4];
                    ldm_x4(b, b2Base + (h * 2 + p) * 16 * 272 + s * 32);
                    mma_f16(acc2[2 * p],     mreg[s], b[0], b[1]);
                    mma_f16(acc2[2 * p + 1], mreg[s], b[2], b[3]);
                }
            }
#pragma unroll
            for (int j = 0; j < 4; j++) {
                int col = q * 64 + h * 32 + j * 8 + 2 * c;
                float2 ha = *(const float2*)(hxa + col);
                red2(Za + col, acc2[j][0] * ha.x, acc2[j][1] * ha.y);
                float2 hb = *(const float2*)(hxb + col);
                red2(Zb + col, acc2[j][2] * hb.x, acc2[j][3] * hb.y);
            }
        }
        CP_WAIT(0);
        __syncthreads();
    }
}

// ---------------- launcher --------------------------------------------------
extern "C" void kernel_launch(void* const* d_in, const int* in_sizes, int n_in,
                              void* d_out, int out_size)
{
    const float* elec = (const float*)d_in[0];
    const float* nuc  = (const float*)d_in[1];
    const float *dist[3], *w1[3], *b1[3], *w2[3], *g[3];

    bool dictOrder = (in_sizes[3] == DF * MID);
    if (dictOrder) {
        const int base[3] = {2, 7, 12};
        for (int tI = 0; tI < 3; tI++) {
            dist[tI] = (const float*)d_in[base[tI] + 0];
            w1[tI]   = (const float*)d_in[base[tI] + 1];
            b1[tI]   = (const float*)d_in[base[tI] + 2];
            w2[tI]   = (const float*)d_in[base[tI] + 3];
            g[tI]    = (const float*)d_in[base[tI] + 4];
        }
    } else {
        for (int tI = 0; tI < 3; tI++) {
            dist[tI] = (const float*)d_in[2 + tI];
            w1[tI]   = (const float*)d_in[5 + 3 * tI];
            b1[tI]   = (const float*)d_in[6 + 3 * tI];
            w2[tI]   = (const float*)d_in[7 + 3 * tI];
            g[tI]    = (const float*)d_in[14 + tI];
        }
    }
    const float* h_w     = (const float*)d_in[17];
    const int*   send[3] = {(const int*)d_in[18], (const int*)d_in[19], (const int*)d_in[20]};
    const int*   recv[3] = {(const int*)d_in[21], (const int*)d_in[22], (const int*)d_in[23]};
    const int    E = in_sizes[2] / DF;
    const int    nblk = E / 128;

    float *HX, *Z;
    __half *Zh, *ELh, *HWh, *GTh;
    cudaGetSymbolAddress((void**)&HX,  g_HX);
    cudaGetSymbolAddress((void**)&Z,   g_Z);
    cudaGetSymbolAddress((void**)&Zh,  g_Zh);
    cudaGetSymbolAddress((void**)&ELh, g_elech);
    cudaGetSymbolAddress((void**)&HWh, g_hwh);
    cudaGetSymbolAddress((void**)&GTh, g_GTh);

    cudaFuncSetAttribute(edge_fused, cudaFuncAttributeMaxDynamicSharedMemorySize, SMEM_EDGE);
    cudaFuncSetAttribute(gemm_h, cudaFuncAttributeMaxDynamicSharedMemorySize, GSM_TOT);

    cudaMemsetAsync(Z, 0, sizeof(float) * N_ELEC * 3 * KER);

    prep_weights<<<3, 256>>>(w1[0], w1[1], w1[2], w2[0], w2[1], w2[2],
                             g[0], g[1], g[2], h_w);

    // electrons -> fp16
    {
        int n4 = N_ELEC * EMB / 4;
        f2h<<<(n4 + 255) / 256, 256>>>((const float4*)elec, (uint2*)ELh, n4);
    }
    // HX = elec @ h_w  (fp16 mma)
    {
        dim3 grid(2, N_ELEC / 64);
        gemm_h<<<grid, 256, GSM_TOT>>>(ELh, EMB, HWh, 264, nullptr, HX);
    }
    // fused fp16-mma edge kernel, all 3 types
    edge_fused<<<3 * nblk, 256, SMEM_EDGE>>>(dist[0], dist[1], dist[2],
                                             b1[0], b1[1], b1[2],
                                             HX, nuc,
                                             send[0], send[1], send[2],
                                             recv[0], recv[1], recv[2],
                                             Z, nblk);
    // Z -> fp16
    {
        int n4 = N_ELEC * 3 * KER / 4;
        f2h<<<(n4 + 255) / 256, 256>>>((const float4*)Z, (uint2*)Zh, n4);
    }
    // out = elec + Z @ Gcat  (fp16 mma)
    {
        dim3 grid(2, N_ELEC / 64);
        gemm_h<<<grid, 256, GSM_TOT>>>(Zh, 3 * KER, GTh, 776, elec, (float*)d_out);
    }
}

// round 9
// speedup vs baseline: 3.0241x; 1.0771x over previous
#include <cuda_runtime.h>
#include <cuda_fp16.h>
#include <math.h>
#include <stdint.h>

#define N_ELEC 8192
#define N_NUC  512
#define EMB    256
#define KER    256
#define DF     64
#define MID    128

// ---------------- scratch (device globals; no allocations allowed) ----------
__device__ __align__(16) float  g_HX[N_ELEC * KER];
__device__ __align__(16) float  g_Z[N_ELEC * 3 * KER];
__device__ __align__(16) __half g_Zh[N_ELEC * 3 * KER];     // fp16 copy of Z
__device__ __align__(16) __half g_elech[N_ELEC * EMB];      // fp16 electrons
// fp16 weight images, n-major, k contiguous, padded row strides.
// N-columns of w2 / h_w / Gcat are perm16-permuted so the mma epilogue owns
// 4 consecutive logical columns per thread (enables red.v4 / STG.128).
__device__ __align__(16) __half g_w1Th[3][128 * 72];
__device__ __align__(16) __half g_w2Th[3][256 * 136];
__device__ __align__(16) __half g_hwh[256 * 264];           // h_w^T  [n=KER][k pad 264]
__device__ __align__(16) __half g_GTh[256 * 776];           // Gcat^T [n=EMB][k pad 776]

// physical fragment slot (8*ntp + 2c + e within 16-block) -> logical col 4c+2ntp+e
__device__ __host__ __forceinline__ int perm16(int n) {
    int c = (n >> 1) & 3, e = n & 1, ntp = (n >> 3) & 1;
    return (n & ~15) | (c << 2) | (ntp << 1) | e;
}

// ---------------- helpers ---------------------------------------------------
__device__ __forceinline__ void ldm_x4(uint32_t r[4], uint32_t saddr) {
    asm volatile("ldmatrix.sync.aligned.m8n8.x4.shared.b16 {%0,%1,%2,%3}, [%4];"
                 : "=r"(r[0]), "=r"(r[1]), "=r"(r[2]), "=r"(r[3]) : "r"(saddr));
}
__device__ __forceinline__ void mma_f16(float acc[4], const uint32_t a[4],
                                        uint32_t b0, uint32_t b1) {
    asm volatile(
        "mma.sync.aligned.m16n8k16.row.col.f32.f16.f16.f32 "
        "{%0,%1,%2,%3}, {%4,%5,%6,%7}, {%8,%9}, {%0,%1,%2,%3};"
        : "+f"(acc[0]), "+f"(acc[1]), "+f"(acc[2]), "+f"(acc[3])
        : "r"(a[0]), "r"(a[1]), "r"(a[2]), "r"(a[3]), "r"(b0), "r"(b1));
}
__device__ __forceinline__ void red4(float* p, float x, float y, float z, float w) {
    asm volatile("red.global.add.v4.f32 [%0], {%1, %2, %3, %4};"
                 :: "l"(p), "f"(x), "f"(y), "f"(z), "f"(w) : "memory");
}
__device__ __forceinline__ void cp16(uint32_t saddr, const void* g) {
    asm volatile("cp.async.cg.shared.global [%0], [%1], 16;" :: "r"(saddr), "l"(g));
}
#define CP_COMMIT() asm volatile("cp.async.commit_group;" ::: "memory")
#define CP_WAIT(n)  asm volatile("cp.async.wait_group %0;" :: "n"(n) : "memory")

__device__ __forceinline__ uint32_t smem_u32(const void* p) {
    uint32_t a;
    asm("{ .reg .u64 t; cvta.to.shared.u64 t, %1; cvt.u32.u64 %0, t; }" : "=r"(a) : "l"(p));
    return a;
}
__device__ __forceinline__ uint32_t packh2(float x, float y) {   // lo=x, hi=y
    uint32_t r;
    asm("cvt.rn.f16x2.f32 %0, %1, %2;" : "=r"(r) : "f"(y), "f"(x));
    return r;
}
__device__ __forceinline__ float sspf(float x) {
    float sp = (x > 0.f) ? (x + log1pf(expf(-x))) : log1pf(expf(x));
    return sp - 0.69314718055994531f;
}

// ================= elementwise fp32 -> fp16 =================================
__global__ void f2h(const float4* __restrict__ src, uint2* __restrict__ dst, int n4) {
    int i = blockIdx.x * blockDim.x + threadIdx.x;
    if (i < n4) {
        float4 v = src[i];
        uint2 h;
        h.x = packh2(v.x, v.y);
        h.y = packh2(v.z, v.w);
        dst[i] = h;
    }
}

// ================= weight prep: transpose + fp16 (+perm16 on n) =============
__global__ void prep_weights(const float* __restrict__ w1_0, const float* __restrict__ w1_1,
                             const float* __restrict__ w1_2,
                             const float* __restrict__ w2_0, const float* __restrict__ w2_1,
                             const float* __restrict__ w2_2,
                             const float* __restrict__ g_0, const float* __restrict__ g_1,
                             const float* __restrict__ g_2,
                             const float* __restrict__ h_w)
{
    int ty = blockIdx.x;
    const float* w1 = (ty == 0) ? w1_0 : (ty == 1) ? w1_1 : w1_2;
    const float* w2 = (ty == 0) ? w2_0 : (ty == 1) ? w2_1 : w2_2;
    const float* gg = (ty == 0) ? g_0  : (ty == 1) ? g_1  : g_2;
    // w1: MID dim NOT permuted (must match stage-2 k ordering / mreg identity)
    for (int i = threadIdx.x; i < 128 * 64; i += blockDim.x) {
        int n = i >> 6, k = i & 63;
        g_w1Th[ty][n * 72 + k] = __float2half(w1[k * 128 + n]);
    }
    // w2: output KER columns permuted
    for (int i = threadIdx.x; i < 256 * 128; i += blockDim.x) {
        int n = i >> 7, k = i & 127;
        g_w2Th[ty][n * 136 + k] = __float2half(w2[k * 256 + perm16(n)]);
    }
    // Gcat^T image (EMB output cols permuted)
    for (int i = threadIdx.x; i < 256 * 256; i += blockDim.x) {
        int n = i >> 8, kk = i & 255;
        g_GTh[n * 776 + ty * 256 + kk] = __float2half(gg[kk * 256 + perm16(n)]);
    }
    // h_w^T image (KER output cols permuted), block 0 only
    if (ty == 0)
        for (int i = threadIdx.x; i < 256 * 256; i += blockDim.x) {
            int n = i >> 8, k = i & 255;
            g_hwh[n * 264 + k] = __float2half(h_w[k * 256 + perm16(n)]);
        }
}

// ================= fp16 tensor-core GEMM: Out[M,256] = (Cin?) + Ah @ Bh^T ===
#define GSM_A0 0
#define GSM_A1 9216
#define GSM_B0 18432
#define GSM_B1 36864
#define GSM_TOT 55296

__global__ void __launch_bounds__(256, 3)
gemm_h(const __half* __restrict__ A, int K,
       const __half* __restrict__ B, int Kpad,
       const float* __restrict__ Cin, float* __restrict__ Out)
{
    extern __shared__ char smem[];
    const uint32_t sbase = smem_u32(smem);
    const int t = threadIdx.x, warp = t >> 5, lane = t & 31;
    const int wm = warp & 3, wn = warp >> 2;
    const int g = lane >> 2, c = lane & 3;
    const int n0 = blockIdx.x * 128, m0 = blockIdx.y * 64;
    const int nch = K / 64;

    const int lrowA = (lane & 7) + ((lane >> 3) & 1) * 8;
    const int lkA   = (lane >> 4) * 8;
    const int lrowB = ((lane >> 4) << 3) + (lane & 7);
    const int lkB   = ((lane >> 3) & 1) * 8;

    float acc[8][4];
#pragma unroll
    for (int j = 0; j < 8; j++)
#pragma unroll
        for (int p = 0; p < 4; p++) acc[j][p] = 0.f;

#define LOAD_CHUNK(ch) do {                                                     \
        uint32_t abuf = sbase + (((ch) & 1) ? GSM_A1 : GSM_A0);                 \
        uint32_t bbuf = sbase + (((ch) & 1) ? GSM_B1 : GSM_B0);                 \
        const char* ag = (const char*)(A + (long)m0 * K + (ch) * 64);           \
        _Pragma("unroll")                                                       \
        for (int i = 0; i < 2; i++) {                                           \
            int idx = t + 256 * i, row = idx >> 3, cc = idx & 7;                \
            cp16(abuf + row * 144 + cc * 16, ag + (long)row * K * 2 + cc * 16); \
        }                                                                       \
        const char* bg = (const char*)(B + (long)n0 * Kpad + (ch) * 64);        \
        _Pragma("unroll")                                                       \
        for (int i = 0; i < 4; i++) {                                           \
            int idx = t + 256 * i, row = idx >> 3, cc = idx & 7;                \
            cp16(bbuf + row * 144 + cc * 16, bg + (long)row * Kpad * 2 + cc * 16); \
        }                                                                       \
        CP_COMMIT();                                                            \
    } while (0)

    LOAD_CHUNK(0);
    for (int ch = 0; ch < nch; ch++) {
        if (ch + 1 < nch) { LOAD_CHUNK(ch + 1); CP_WAIT(1); }
        else              { CP_WAIT(0); }
        __syncthreads();
        uint32_t abuf = sbase + ((ch & 1) ? GSM_A1 : GSM_A0);
        uint32_t bbuf = sbase + ((ch & 1) ? GSM_B1 : GSM_B0);
        uint32_t aB = abuf + (wm * 16 + lrowA) * 144 + lkA * 2;
        uint32_t bB = bbuf + (wn * 64 + lrowB) * 144 + lkB * 2;
#pragma unroll
        for (int s = 0; s < 4; s++) {
            uint32_t a[4];
            ldm_x4(a, aB + s * 32);
#pragma unroll
            for (int p = 0; p < 4; p++) {
                uint32_t b[4];
                ldm_x4(b, bB + p * 16 * 144 + s * 32);
                mma_f16(acc[2 * p],     a, b[0], b[1]);
                mma_f16(acc[2 * p + 1], a, b[2], b[3]);
            }
        }
        __syncthreads();
    }

    // epilogue (perm16 B image): thread owns 4 consecutive cols per nt-pair
    int ra = m0 + wm * 16 + g, rb = ra + 8;
#pragma unroll
    for (int p = 0; p < 4; p++) {
        int col = n0 + wn * 64 + p * 16 + 4 * c;
        float4 v0 = make_float4(acc[2*p][0], acc[2*p][1], acc[2*p+1][0], acc[2*p+1][1]);
        float4 v1 = make_float4(acc[2*p][2], acc[2*p][3], acc[2*p+1][2], acc[2*p+1][3]);
        if (Cin) {
            float4 c0 = *(const float4*)(Cin + (long)ra * 256 + col);
            float4 c1 = *(const float4*)(Cin + (long)rb * 256 + col);
            v0.x += c0.x; v0.y += c0.y; v0.z += c0.z; v0.w += c0.w;
            v1.x += c1.x; v1.y += c1.y; v1.z += c1.z; v1.w += c1.w;
        }
        *(float4*)(Out + (long)ra * 256 + col) = v0;
        *(float4*)(Out + (long)rb * 256 + col) = v1;
    }
}

// ================= fused fp16 mma edge kernel ===============================
#define SH_B1    0
#define SH_SEND  512
#define SH_RECV  1024
#define SH_DIST  1536
#define SH_W1T   19968
#define SH_W2A   38400
#define SH_W2B   55808
#define SMEM_EDGE 73216

__global__ void __launch_bounds__(256, 3)
edge_fused(const float* __restrict__ dist0, const float* __restrict__ dist1,
           const float* __restrict__ dist2,
           const float* __restrict__ b1_0, const float* __restrict__ b1_1,
           const float* __restrict__ b1_2,
           const float* __restrict__ HX, const float* __restrict__ nuc,
           const int* __restrict__ s0, const int* __restrict__ s1, const int* __restrict__ s2,
           const int* __restrict__ r0p, const int* __restrict__ r1p, const int* __restrict__ r2p,
           float* __restrict__ Z, int nblk)
{
    extern __shared__ char smem[];
    float* smF = (float*)smem;
    const uint32_t sbase = smem_u32(smem);
    const int t = threadIdx.x, warp = t >> 5, lane = t & 31;
    const int g = lane >> 2, c = lane & 3;
    const int wr0 = warp * 16;

    const int ty  = blockIdx.x / nblk;
    const int blk = blockIdx.x - ty * nblk;
    const float* dist  = (ty == 0) ? dist0 : (ty == 1) ? dist1 : dist2;
    const float* b1    = (ty == 0) ? b1_0  : (ty == 1) ? b1_1  : b1_2;
    const int*   snd   = (ty == 0) ? s0 : (ty == 1) ? s1 : s2;
    const int*   rcv   = (ty == 0) ? r0p : (ty == 1) ? r1p : r2p;
    const float* hxsrc = (ty == 2) ? nuc : HX;
    const int    zoff  = ty * KER;
    const long   e0    = (long)blk * 128;
    const __half* w1T  = g_w1Th[ty];
    const __half* w2T  = g_w2Th[ty];

    if (t < 128) {
        smF[(SH_B1 >> 2) + t] = b1[t];
        ((int*)smem)[(SH_SEND >> 2) + t] = snd[e0 + t];
        ((int*)smem)[(SH_RECV >> 2) + t] = rcv[e0 + t];
    }
    {
        int row = t >> 1, part = t & 1;
        const float4* dr = (const float4*)(dist + (e0 + row) * DF);
        char* dst = smem + SH_DIST + row * 144;
#pragma unroll
        for (int j = 0; j < 8; j++) {
            int c4 = part * 8 + j;
            float4 v = dr[c4];
            uint2 h;
            h.x = packh2(v.x, v.y);
            h.y = packh2(v.z, v.w);
            *(uint2*)(dst + c4 * 8) = h;
        }
    }
    for (int i = t; i < 1152; i += 256)
        cp16(sbase + SH_W1T + i * 16, (const char*)w1T + i * 16);
    CP_COMMIT();
    for (int i = t; i < 1088; i += 256)
        cp16(sbase + SH_W2A + i * 16, (const char*)w2T + i * 16);
    CP_COMMIT();

    CP_WAIT(1);
    __syncthreads();

    const int lrowA = (lane & 7) + ((lane >> 3) & 1) * 8;
    const int lkA   = (lane >> 4) * 8;
    const int lrowB = ((lane >> 4) << 3) + (lane & 7);
    const int lkB   = ((lane >> 3) & 1) * 8;
    const uint32_t aBase  = sbase + SH_DIST + (wr0 + lrowA) * 144 + lkA * 2;
    const uint32_t b1Base = sbase + SH_W1T + lrowB * 144 + lkB * 2;

    uint32_t mreg[8][4];
#pragma unroll
    for (int pass = 0; pass < 2; pass++) {
        float acc[8][4];
#pragma unroll
        for (int j = 0; j < 8; j++)
#pragma unroll
            for (int q = 0; q < 4; q++) acc[j][q] = 0.f;
#pragma unroll
        for (int s = 0; s < 4; s++) {
            uint32_t a[4];
            ldm_x4(a, aBase + s * 32);
#pragma unroll
            for (int p = 0; p < 4; p++) {
                uint32_t b[4];
                ldm_x4(b, b1Base + (pass * 4 + p) * 16 * 144 + s * 32);
                mma_f16(acc[2 * p],     a, b[0], b[1]);
                mma_f16(acc[2 * p + 1], a, b[2], b[3]);
            }
        }
        const float* sB1 = smF + (SH_B1 >> 2);
#pragma unroll
        for (int p = 0; p < 4; p++) {
            int nt0 = pass * 8 + 2 * p, nt1 = nt0 + 1;
            float bA0 = sB1[nt0 * 8 + 2 * c], bA1 = sB1[nt0 * 8 + 2 * c + 1];
            float bB0 = sB1[nt1 * 8 + 2 * c], bB1 = sB1[nt1 * 8 + 2 * c + 1];
            int s2i = pass * 4 + p;
            mreg[s2i][0] = packh2(sspf(acc[2*p][0] + bA0),   sspf(acc[2*p][1] + bA1));
            mreg[s2i][1] = packh2(sspf(acc[2*p][2] + bA0),   sspf(acc[2*p][3] + bA1));
            mreg[s2i][2] = packh2(sspf(acc[2*p+1][0] + bB0), sspf(acc[2*p+1][1] + bB1));
            mreg[s2i][3] = packh2(sspf(acc[2*p+1][2] + bB0), sspf(acc[2*p+1][3] + bB1));
        }
    }

    const int ra = wr0 + g, rb = wr0 + g + 8;
    const int sa = ((int*)smem)[(SH_SEND >> 2) + ra];
    const int sb = ((int*)smem)[(SH_SEND >> 2) + rb];
    const int qa = ((int*)smem)[(SH_RECV >> 2) + ra];
    const int qb = ((int*)smem)[(SH_RECV >> 2) + rb];
    const float* hxa = hxsrc + (long)sa * KER;
    const float* hxb = hxsrc + (long)sb * KER;
    float* Za = Z + (long)qa * (3 * KER) + zoff;
    float* Zb = Z + (long)qb * (3 * KER) + zoff;

    CP_WAIT(0);
    __syncthreads();

#pragma unroll
    for (int q = 0; q < 4; q++) {
        if (q < 3) {
            uint32_t dstq = sbase + (((q + 1) & 1) ? SH_W2B : SH_W2A);
            const char* srcq = (const char*)(w2T + (long)(q + 1) * 64 * 136);
            for (int i = t; i < 1088; i += 256) cp16(dstq + i * 16, srcq + i * 16);
            CP_COMMIT();
        }
        const uint32_t swq = sbase + ((q & 1) ? SH_W2B : SH_W2A);
        const uint32_t b2Base = swq + lrowB * 272 + lkB * 2;
#pragma unroll
        for (int h = 0; h < 2; h++) {
            float acc2[4][4];
#pragma unroll
            for (int j = 0; j < 4; j++)
#pragma unroll
                for (int p = 0; p < 4; p++) acc2[j][p] = 0.f;
#pragma unroll
            for (int s = 0; s < 8; s++) {
#pragma unroll
                for (int p = 0; p < 2; p++) {
                    uint32_t b[4];
                    ldm_x4(b, b2Base + (h * 2 + p) * 16 * 272 + s * 32);
                    mma_f16(acc2[2 * p],     mreg[s], b[0], b[1]);
                    mma_f16(acc2[2 * p + 1], mreg[s], b[2], b[3]);
                }
            }
            // epilogue (perm16 w2 image): 4 consecutive cols per nt-pair
#pragma unroll
            for (int p = 0; p < 2; p++) {
                int base = q * 64 + h * 32 + p * 16 + 4 * c;
                float4 ha = *(const float4*)(hxa + base);
                red4(Za + base, acc2[2*p][0] * ha.x, acc2[2*p][1] * ha.y,
                                acc2[2*p+1][0] * ha.z, acc2[2*p+1][1] * ha.w);
                float4 hb = *(const float4*)(hxb + base);
                red4(Zb + base, acc2[2*p][2] * hb.x, acc2[2*p][3] * hb.y,
                                acc2[2*p+1][2] * hb.z, acc2[2*p+1][3] * hb.w);
            }
        }
        CP_WAIT(0);
        __syncthreads();
    }
}

// ---------------- launcher --------------------------------------------------
extern "C" void kernel_launch(void* const* d_in, const int* in_sizes, int n_in,
                              void* d_out, int out_size)
{
    const float* elec = (const float*)d_in[0];
    const float* nuc  = (const float*)d_in[1];
    const float *dist[3], *w1[3], *b1[3], *w2[3], *g[3];

    bool dictOrder = (in_sizes[3] == DF * MID);
    if (dictOrder) {
        const int base[3] = {2, 7, 12};
        for (int tI = 0; tI < 3; tI++) {
            dist[tI] = (const float*)d_in[base[tI] + 0];
            w1[tI]   = (const float*)d_in[base[tI] + 1];
            b1[tI]   = (const float*)d_in[base[tI] + 2];
            w2[tI]   = (const float*)d_in[base[tI] + 3];
            g[tI]    = (const float*)d_in[base[tI] + 4];
        }
    } else {
        for (int tI = 0; tI < 3; tI++) {
            dist[tI] = (const float*)d_in[2 + tI];
            w1[tI]   = (const float*)d_in[5 + 3 * tI];
            b1[tI]   = (const float*)d_in[6 + 3 * tI];
            w2[tI]   = (const float*)d_in[7 + 3 * tI];
            g[tI]    = (const float*)d_in[14 + tI];
        }
    }
    const float* h_w     = (const float*)d_in[17];
    const int*   send[3] = {(const int*)d_in[18], (const int*)d_in[19], (const int*)d_in[20]};
    const int*   recv[3] = {(const int*)d_in[21], (const int*)d_in[22], (const int*)d_in[23]};
    const int    E = in_sizes[2] / DF;
    const int    nblk = E / 128;

    float *HX, *Z;
    __half *Zh, *ELh, *HWh, *GTh;
    cudaGetSymbolAddress((void**)&HX,  g_HX);
    cudaGetSymbolAddress((void**)&Z,   g_Z);
    cudaGetSymbolAddress((void**)&Zh,  g_Zh);
    cudaGetSymbolAddress((void**)&ELh, g_elech);
    cudaGetSymbolAddress((void**)&HWh, g_hwh);
    cudaGetSymbolAddress((void**)&GTh, g_GTh);

    cudaFuncSetAttribute(edge_fused, cudaFuncAttributeMaxDynamicSharedMemorySize, SMEM_EDGE);
    cudaFuncSetAttribute(gemm_h, cudaFuncAttributeMaxDynamicSharedMemorySize, GSM_TOT);

    cudaMemsetAsync(Z, 0, sizeof(float) * N_ELEC * 3 * KER);

    prep_weights<<<3, 256>>>(w1[0], w1[1], w1[2], w2[0], w2[1], w2[2],
                             g[0], g[1], g[2], h_w);

    // electrons -> fp16
    {
        int n4 = N_ELEC * EMB / 4;
        f2h<<<(n4 + 255) / 256, 256>>>((const float4*)elec, (uint2*)ELh, n4);
    }
    // HX = elec @ h_w  (fp16 mma)
    {
        dim3 grid(2, N_ELEC / 64);
        gemm_h<<<grid, 256, GSM_TOT>>>(ELh, EMB, HWh, 264, nullptr, HX);
    }
    // fused fp16-mma edge kernel, all 3 types
    edge_fused<<<3 * nblk, 256, SMEM_EDGE>>>(dist[0], dist[1], dist[2],
                                             b1[0], b1[1], b1[2],
                                             HX, nuc,
                                             send[0], send[1], send[2],
                                             recv[0], recv[1], recv[2],
                                             Z, nblk);
    // Z -> fp16
    {
        int n4 = N_ELEC * 3 * KER / 4;
        f2h<<<(n4 + 255) / 256, 256>>>((const float4*)Z, (uint2*)Zh, n4);
    }
    // out = elec + Z @ Gcat  (fp16 mma)
    {
        dim3 grid(2, N_ELEC / 64);
        gemm_h<<<grid, 256, GSM_TOT>>>(Zh, 3 * KER, GTh, 776, elec, (float*)d_out);
    }
}

// round 10
// speedup vs baseline: 3.1445x; 1.0398x over previous
#include <cuda_runtime.h>
#include <cuda_fp16.h>
#include <math.h>
#include <stdint.h>

#define N_ELEC 8192
#define N_NUC  512
#define EMB    256
#define KER    256
#define DF     64
#define MID    128

// ---------------- scratch (device globals; no allocations allowed) ----------
__device__ __align__(16) float  g_HX[N_ELEC * KER];
__device__ __align__(16) float  g_Z[N_ELEC * 3 * KER];
__device__ __align__(16) __half g_Zh[N_ELEC * 3 * KER];
__device__ __align__(16) __half g_elech[N_ELEC * EMB];
// edge-kernel weight images in per-lane FRAGMENT order:
//   slot [nblk16][kstep16][lane][8 halves] = the 4 b32 regs of lane's B fragment
__device__ __align__(16) __half g_w1Th[3][128 * 64];        // 8 nblk x 4 ks
__device__ __align__(16) __half g_w2Th[3][256 * 128];       // 16 nblk x 8 ks
// gemm_h images (n-major rows, perm16'd cols) — unchanged scheme
__device__ __align__(16) __half g_hwh[256 * 264];
__device__ __align__(16) __half g_GTh[256 * 776];

// physical fragment col (within 16-block: ntp*8 + 2c + e) -> logical col 4c+2ntp+e
__device__ __host__ __forceinline__ int perm16(int n) {
    int c = (n >> 1) & 3, e = n & 1, ntp = (n >> 3) & 1;
    return (n & ~15) | (c << 2) | (ntp << 1) | e;
}

// ---------------- helpers ---------------------------------------------------
__device__ __forceinline__ void ldm_x4(uint32_t r[4], uint32_t saddr) {
    asm volatile("ldmatrix.sync.aligned.m8n8.x4.shared.b16 {%0,%1,%2,%3}, [%4];"
                 : "=r"(r[0]), "=r"(r[1]), "=r"(r[2]), "=r"(r[3]) : "r"(saddr));
}
__device__ __forceinline__ uint4 lds128(uint32_t saddr) {
    uint4 v;
    asm volatile("ld.shared.v4.b32 {%0,%1,%2,%3}, [%4];"
                 : "=r"(v.x), "=r"(v.y), "=r"(v.z), "=r"(v.w) : "r"(saddr));
    return v;
}
__device__ __forceinline__ void mma_f16(float acc[4], const uint32_t a[4],
                                        uint32_t b0, uint32_t b1) {
    asm volatile(
        "mma.sync.aligned.m16n8k16.row.col.f32.f16.f16.f32 "
        "{%0,%1,%2,%3}, {%4,%5,%6,%7}, {%8,%9}, {%0,%1,%2,%3};"
        : "+f"(acc[0]), "+f"(acc[1]), "+f"(acc[2]), "+f"(acc[3])
        : "r"(a[0]), "r"(a[1]), "r"(a[2]), "r"(a[3]), "r"(b0), "r"(b1));
}
__device__ __forceinline__ void red4(float* p, float x, float y, float z, float w) {
    asm volatile("red.global.add.v4.f32 [%0], {%1, %2, %3, %4};"
                 :: "l"(p), "f"(x), "f"(y), "f"(z), "f"(w) : "memory");
}
__device__ __forceinline__ void cp16(uint32_t saddr, const void* g) {
    asm volatile("cp.async.cg.shared.global [%0], [%1], 16;" :: "r"(saddr), "l"(g));
}
#define CP_COMMIT() asm volatile("cp.async.commit_group;" ::: "memory")
#define CP_WAIT(n)  asm volatile("cp.async.wait_group %0;" :: "n"(n) : "memory")

__device__ __forceinline__ uint32_t smem_u32(const void* p) {
    uint32_t a;
    asm("{ .reg .u64 t; cvta.to.shared.u64 t, %1; cvt.u32.u64 %0, t; }" : "=r"(a) : "l"(p));
    return a;
}
__device__ __forceinline__ uint32_t packh2(float x, float y) {   // lo=x, hi=y
    uint32_t r;
    asm("cvt.rn.f16x2.f32 %0, %1, %2;" : "=r"(r) : "f"(y), "f"(x));
    return r;
}
__device__ __forceinline__ float sspf(float x) {
    float sp = (x > 0.f) ? (x + log1pf(expf(-x))) : log1pf(expf(x));
    return sp - 0.69314718055994531f;
}

// ================= elementwise fp32 -> fp16 =================================
__global__ void f2h(const float4* __restrict__ src, uint2* __restrict__ dst, int n4) {
    int i = blockIdx.x * blockDim.x + threadIdx.x;
    if (i < n4) {
        float4 v = src[i];
        uint2 h;
        h.x = packh2(v.x, v.y);
        h.y = packh2(v.z, v.w);
        dst[i] = h;
    }
}

// ================= weight prep ==============================================
// Edge images in fragment order. Slot decomposition (halves index i):
//   h = i&7 (reg = h>>1, e = h&1), lane = (i>>3)&31 (g = lane>>2, c = lane&3)
//   reg: 0 = nt-even k-low, 1 = nt-even k-high, 2 = nt-odd k-low, 3 = nt-odd k-high
//   k = ks*16 + (reg&1)*8 + 2c + e ;  n_phys(within blk) = (reg>>1)*8 + g
__global__ void prep_weights(const float* __restrict__ w1_0, const float* __restrict__ w1_1,
                             const float* __restrict__ w1_2,
                             const float* __restrict__ w2_0, const float* __restrict__ w2_1,
                             const float* __restrict__ w2_2,
                             const float* __restrict__ g_0, const float* __restrict__ g_1,
                             const float* __restrict__ g_2,
                             const float* __restrict__ h_w)
{
    int ty = blockIdx.x;
    const float* w1 = (ty == 0) ? w1_0 : (ty == 1) ? w1_1 : w1_2;
    const float* w2 = (ty == 0) ? w2_0 : (ty == 1) ? w2_1 : w2_2;
    const float* gg = (ty == 0) ? g_0  : (ty == 1) ? g_1  : g_2;
    // w1 fragment image: MID cols NOT permuted (mreg identity needs phys order)
    for (int i = threadIdx.x; i < 128 * 64; i += blockDim.x) {
        int h = i & 7, lane = (i >> 3) & 31, ks = (i >> 8) & 3, nblk = i >> 10;
        int gl = lane >> 2, cl = lane & 3, reg = h >> 1, e = h & 1;
        int k = ks * 16 + (reg & 1) * 8 + 2 * cl + e;
        int n = nblk * 16 + (reg >> 1) * 8 + gl;
        g_w1Th[ty][i] = __float2half(w1[k * 128 + n]);
    }
    // w2 fragment image: KER cols perm16'd (epilogue red.v4 contiguity)
    for (int i = threadIdx.x; i < 256 * 128; i += blockDim.x) {
        int h = i & 7, lane = (i >> 3) & 31, ks = (i >> 8) & 7, nblk = i >> 11;
        int gl = lane >> 2, cl = lane & 3, reg = h >> 1, e = h & 1;
        int k = ks * 16 + (reg & 1) * 8 + 2 * cl + e;
        int n = nblk * 16 + perm16((reg >> 1) * 8 + gl);
        g_w2Th[ty][i] = __float2half(w2[k * 256 + n]);
    }
    // Gcat^T image (EMB cols permuted) — gemm_h scheme
    for (int i = threadIdx.x; i < 256 * 256; i += blockDim.x) {
        int n = i >> 8, kk = i & 255;
        g_GTh[n * 776 + ty * 256 + kk] = __float2half(gg[kk * 256 + perm16(n)]);
    }
    if (ty == 0)
        for (int i = threadIdx.x; i < 256 * 256; i += blockDim.x) {
            int n = i >> 8, k = i & 255;
            g_hwh[n * 264 + k] = __float2half(h_w[k * 256 + perm16(n)]);
        }
}

// ================= fp16 tensor-core GEMM (unchanged from R9) ================
#define GSM_A0 0
#define GSM_A1 9216
#define GSM_B0 18432
#define GSM_B1 36864
#define GSM_TOT 55296

__global__ void __launch_bounds__(256, 3)
gemm_h(const __half* __restrict__ A, int K,
       const __half* __restrict__ B, int Kpad,
       const float* __restrict__ Cin, float* __restrict__ Out)
{
    extern __shared__ char smem[];
    const uint32_t sbase = smem_u32(smem);
    const int t = threadIdx.x, warp = t >> 5, lane = t & 31;
    const int wm = warp & 3, wn = warp >> 2;
    const int g = lane >> 2, c = lane & 3;
    const int n0 = blockIdx.x * 128, m0 = blockIdx.y * 64;
    const int nch = K / 64;

    const int lrowA = (lane & 7) + ((lane >> 3) & 1) * 8;
    const int lkA   = (lane >> 4) * 8;
    const int lrowB = ((lane >> 4) << 3) + (lane & 7);
    const int lkB   = ((lane >> 3) & 1) * 8;

    float acc[8][4];
#pragma unroll
    for (int j = 0; j < 8; j++)
#pragma unroll
        for (int p = 0; p < 4; p++) acc[j][p] = 0.f;

#define LOAD_CHUNK(ch) do {                                                     \
        uint32_t abuf = sbase + (((ch) & 1) ? GSM_A1 : GSM_A0);                 \
        uint32_t bbuf = sbase + (((ch) & 1) ? GSM_B1 : GSM_B0);                 \
        const char* ag = (const char*)(A + (long)m0 * K + (ch) * 64);           \
        _Pragma("unroll")                                                       \
        for (int i = 0; i < 2; i++) {                                           \
            int idx = t + 256 * i, row = idx >> 3, cc = idx & 7;                \
            cp16(abuf + row * 144 + cc * 16, ag + (long)row * K * 2 + cc * 16); \
        }                                                                       \
        const char* bg = (const char*)(B + (long)n0 * Kpad + (ch) * 64);        \
        _Pragma("unroll")                                                       \
        for (int i = 0; i < 4; i++) {                                           \
            int idx = t + 256 * i, row = idx >> 3, cc = idx & 7;                \
            cp16(bbuf + row * 144 + cc * 16, bg + (long)row * Kpad * 2 + cc * 16); \
        }                                                                       \
        CP_COMMIT();                                                            \
    } while (0)

    LOAD_CHUNK(0);
    for (int ch = 0; ch < nch; ch++) {
        if (ch + 1 < nch) { LOAD_CHUNK(ch + 1); CP_WAIT(1); }
        else              { CP_WAIT(0); }
        __syncthreads();
        uint32_t abuf = sbase + ((ch & 1) ? GSM_A1 : GSM_A0);
        uint32_t bbuf = sbase + ((ch & 1) ? GSM_B1 : GSM_B0);
        uint32_t aB = abuf + (wm * 16 + lrowA) * 144 + lkA * 2;
        uint32_t bB = bbuf + (wn * 64 + lrowB) * 144 + lkB * 2;
#pragma unroll
        for (int s = 0; s < 4; s++) {
            uint32_t a[4];
            ldm_x4(a, aB + s * 32);
#pragma unroll
            for (int p = 0; p < 4; p++) {
                uint32_t b[4];
                ldm_x4(b, bB + p * 16 * 144 + s * 32);
                mma_f16(acc[2 * p],     a, b[0], b[1]);
                mma_f16(acc[2 * p + 1], a, b[2], b[3]);
            }
        }
        __syncthreads();
    }

    int ra = m0 + wm * 16 + g, rb = ra + 8;
#pragma unroll
    for (int p = 0; p < 4; p++) {
        int col = n0 + wn * 64 + p * 16 + 4 * c;
        float4 v0 = make_float4(acc[2*p][0], acc[2*p][1], acc[2*p+1][0], acc[2*p+1][1]);
        float4 v1 = make_float4(acc[2*p][2], acc[2*p][3], acc[2*p+1][2], acc[2*p+1][3]);
        if (Cin) {
            float4 c0 = *(const float4*)(Cin + (long)ra * 256 + col);
            float4 c1 = *(const float4*)(Cin + (long)rb * 256 + col);
            v0.x += c0.x; v0.y += c0.y; v0.z += c0.z; v0.w += c0.w;
            v1.x += c1.x; v1.y += c1.y; v1.z += c1.z; v1.w += c1.w;
        }
        *(float4*)(Out + (long)ra * 256 + col) = v0;
        *(float4*)(Out + (long)rb * 256 + col) = v1;
    }
}

// ================= fused fp16 mma edge kernel ===============================
// smem bytes:
//   0: b1[128] f32   512: send[128]   1024: recv[128]
//   1536:  dist half [128][stride 144B]  (18432) -> 19968
//   19968: w1 fragment image (16384)     -> 36352
//   36352: w2 quarter buf A (16384)      -> 52736
//   52736: w2 quarter buf B (16384)      -> 69120
#define SH_B1    0
#define SH_SEND  512
#define SH_RECV  1024
#define SH_DIST  1536
#define SH_W1T   19968
#define SH_W2A   36352
#define SH_W2B   52736
#define SMEM_EDGE 69120

__global__ void __launch_bounds__(256, 3)
edge_fused(const float* __restrict__ dist0, const float* __restrict__ dist1,
           const float* __restrict__ dist2,
           const float* __restrict__ b1_0, const float* __restrict__ b1_1,
           const float* __restrict__ b1_2,
           const float* __restrict__ HX, const float* __restrict__ nuc,
           const int* __restrict__ s0, const int* __restrict__ s1, const int* __restrict__ s2,
           const int* __restrict__ r0p, const int* __restrict__ r1p, const int* __restrict__ r2p,
           float* __restrict__ Z, int nblk)
{
    extern __shared__ char smem[];
    float* smF = (float*)smem;
    const uint32_t sbase = smem_u32(smem);
    const int t = threadIdx.x, warp = t >> 5, lane = t & 31;
    const int g = lane >> 2, c = lane & 3;
    const int wr0 = warp * 16;

    const int ty  = blockIdx.x / nblk;
    const int blk = blockIdx.x - ty * nblk;
    const float* dist  = (ty == 0) ? dist0 : (ty == 1) ? dist1 : dist2;
    const float* b1    = (ty == 0) ? b1_0  : (ty == 1) ? b1_1  : b1_2;
    const int*   snd   = (ty == 0) ? s0 : (ty == 1) ? s1 : s2;
    const int*   rcv   = (ty == 0) ? r0p : (ty == 1) ? r1p : r2p;
    const float* hxsrc = (ty == 2) ? nuc : HX;
    const int    zoff  = ty * KER;
    const long   e0    = (long)blk * 128;
    const __half* w1T  = g_w1Th[ty];
    const __half* w2T  = g_w2Th[ty];

    // ---- fill ----
    if (t < 128) {
        smF[(SH_B1 >> 2) + t] = b1[t];
        ((int*)smem)[(SH_SEND >> 2) + t] = snd[e0 + t];
        ((int*)smem)[(SH_RECV >> 2) + t] = rcv[e0 + t];
    }
    {
        int row = t >> 1, part = t & 1;
        const float4* dr = (const float4*)(dist + (e0 + row) * DF);
        char* dst = smem + SH_DIST + row * 144;
#pragma unroll
        for (int j = 0; j < 8; j++) {
            int c4 = part * 8 + j;
            float4 v = dr[c4];
            uint2 h;
            h.x = packh2(v.x, v.y);
            h.y = packh2(v.z, v.w);
            *(uint2*)(dst + c4 * 8) = h;
        }
    }
    // w1 image: 16384B = 1024 x16B (group 0)
#pragma unroll
    for (int i = 0; i < 4; i++)
        cp16(sbase + SH_W1T + (t + 256 * i) * 16, (const char*)w1T + (t + 256 * i) * 16);
    CP_COMMIT();
    // w2 quarter 0 (group 1)
#pragma unroll
    for (int i = 0; i < 4; i++)
        cp16(sbase + SH_W2A + (t + 256 * i) * 16, (const char*)w2T + (t + 256 * i) * 16);
    CP_COMMIT();

    CP_WAIT(1);
    __syncthreads();

    const int lrowA = (lane & 7) + ((lane >> 3) & 1) * 8;
    const int lkA   = (lane >> 4) * 8;
    const uint32_t aBase = sbase + SH_DIST + (wr0 + lrowA) * 144 + lkA * 2;
    const uint32_t w1s   = sbase + SH_W1T + lane * 16;

    // ---- stage 1: fragment-image B via LDS.128 (imm offsets) ----
    uint32_t mreg[8][4];
#pragma unroll
    for (int pass = 0; pass < 2; pass++) {
        float acc[8][4];
#pragma unroll
        for (int j = 0; j < 8; j++)
#pragma unroll
            for (int q = 0; q < 4; q++) acc[j][q] = 0.f;
#pragma unroll
        for (int s = 0; s < 4; s++) {
            uint32_t a[4];
            ldm_x4(a, aBase + s * 32);
#pragma unroll
            for (int p = 0; p < 4; p++) {
                uint4 b = lds128(w1s + ((pass * 4 + p) * 4 + s) * 512);
                mma_f16(acc[2 * p],     a, b.x, b.y);
                mma_f16(acc[2 * p + 1], a, b.z, b.w);
            }
        }
        const float* sB1 = smF + (SH_B1 >> 2);
#pragma unroll
        for (int p = 0; p < 4; p++) {
            int nt0 = pass * 8 + 2 * p, nt1 = nt0 + 1;
            float bA0 = sB1[nt0 * 8 + 2 * c], bA1 = sB1[nt0 * 8 + 2 * c + 1];
            float bB0 = sB1[nt1 * 8 + 2 * c], bB1 = sB1[nt1 * 8 + 2 * c + 1];
            int s2i = pass * 4 + p;
            mreg[s2i][0] = packh2(sspf(acc[2*p][0] + bA0),   sspf(acc[2*p][1] + bA1));
            mreg[s2i][1] = packh2(sspf(acc[2*p][2] + bA0),   sspf(acc[2*p][3] + bA1));
            mreg[s2i][2] = packh2(sspf(acc[2*p+1][0] + bB0), sspf(acc[2*p+1][1] + bB1));
            mreg[s2i][3] = packh2(sspf(acc[2*p+1][2] + bB0), sspf(acc[2*p+1][3] + bB1));
        }
    }

    const int ra = wr0 + g, rb = wr0 + g + 8;
    const int sa = ((int*)smem)[(SH_SEND >> 2) + ra];
    const int sb = ((int*)smem)[(SH_SEND >> 2) + rb];
    const int qa = ((int*)smem)[(SH_RECV >> 2) + ra];
    const int qb = ((int*)smem)[(SH_RECV >> 2) + rb];
    const float* hxa = hxsrc + (long)sa * KER;
    const float* hxb = hxsrc + (long)sb * KER;
    float* Za = Z + (long)qa * (3 * KER) + zoff;
    float* Zb = Z + (long)qb * (3 * KER) + zoff;

    CP_WAIT(0);
    __syncthreads();

    // ---- stage 2: 4 quarters x 4 n-blocks of 16; B via LDS.128 ----
#pragma unroll
    for (int q = 0; q < 4; q++) {
        if (q < 3) {
            uint32_t dstq = sbase + (((q + 1) & 1) ? SH_W2B : SH_W2A);
            const char* srcq = (const char*)(w2T + (long)(q + 1) * 64 * 128);
#pragma unroll
            for (int i = 0; i < 4; i++)
                cp16(dstq + (t + 256 * i) * 16, srcq + (t + 256 * i) * 16);
            CP_COMMIT();
        }
        const uint32_t swq = sbase + ((q & 1) ? SH_W2B : SH_W2A) + lane * 16;
#pragma unroll
        for (int nb = 0; nb < 4; nb++) {
            float acc2[2][4];
#pragma unroll
            for (int j = 0; j < 2; j++)
#pragma unroll
                for (int p = 0; p < 4; p++) acc2[j][p] = 0.f;
#pragma unroll
            for (int s = 0; s < 8; s++) {
                uint4 b = lds128(swq + (nb * 8 + s) * 512);
                mma_f16(acc2[0], mreg[s], b.x, b.y);
                mma_f16(acc2[1], mreg[s], b.z, b.w);
            }
            int base = q * 64 + nb * 16 + 4 * c;
            float4 ha = *(const float4*)(hxa + base);
            red4(Za + base, acc2[0][0] * ha.x, acc2[0][1] * ha.y,
                            acc2[1][0] * ha.z, acc2[1][1] * ha.w);
            float4 hb = *(const float4*)(hxb + base);
            red4(Zb + base, acc2[0][2] * hb.x, acc2[0][3] * hb.y,
                            acc2[1][2] * hb.z, acc2[1][3] * hb.w);
        }
        CP_WAIT(0);
        __syncthreads();
    }
}

// ---------------- launcher --------------------------------------------------
extern "C" void kernel_launch(void* const* d_in, const int* in_sizes, int n_in,
                              void* d_out, int out_size)
{
    const float* elec = (const float*)d_in[0];
    const float* nuc  = (const float*)d_in[1];
    const float *dist[3], *w1[3], *b1[3], *w2[3], *g[3];

    bool dictOrder = (in_sizes[3] == DF * MID);
    if (dictOrder) {
        const int base[3] = {2, 7, 12};
        for (int tI = 0; tI < 3; tI++) {
            dist[tI] = (const float*)d_in[base[tI] + 0];
            w1[tI]   = (const float*)d_in[base[tI] + 1];
            b1[tI]   = (const float*)d_in[base[tI] + 2];
            w2[tI]   = (const float*)d_in[base[tI] + 3];
            g[tI]    = (const float*)d_in[base[tI] + 4];
        }
    } else {
        for (int tI = 0; tI < 3; tI++) {
            dist[tI] = (const float*)d_in[2 + tI];
            w1[tI]   = (const float*)d_in[5 + 3 * tI];
            b1[tI]   = (const float*)d_in[6 + 3 * tI];
            w2[tI]   = (const float*)d_in[7 + 3 * tI];
            g[tI]    = (const float*)d_in[14 + tI];
        }
    }
    const float* h_w     = (const float*)d_in[17];
    const int*   send[3] = {(const int*)d_in[18], (const int*)d_in[19], (const int*)d_in[20]};
    const int*   recv[3] = {(const int*)d_in[21], (const int*)d_in[22], (const int*)d_in[23]};
    const int    E = in_sizes[2] / DF;
    const int    nblk = E / 128;

    float *HX, *Z;
    __half *Zh, *ELh, *HWh, *GTh;
    cudaGetSymbolAddress((void**)&HX,  g_HX);
    cudaGetSymbolAddress((void**)&Z,   g_Z);
    cudaGetSymbolAddress((void**)&Zh,  g_Zh);
    cudaGetSymbolAddress((void**)&ELh, g_elech);
    cudaGetSymbolAddress((void**)&HWh, g_hwh);
    cudaGetSymbolAddress((void**)&GTh, g_GTh);

    cudaFuncSetAttribute(edge_fused, cudaFuncAttributeMaxDynamicSharedMemorySize, SMEM_EDGE);
    cudaFuncSetAttribute(gemm_h, cudaFuncAttributeMaxDynamicSharedMemorySize, GSM_TOT);

    cudaMemsetAsync(Z, 0, sizeof(float) * N_ELEC * 3 * KER);

    prep_weights<<<3, 256>>>(w1[0], w1[1], w1[2], w2[0], w2[1], w2[2],
                             g[0], g[1], g[2], h_w);

    // electrons -> fp16
    {
        int n4 = N_ELEC * EMB / 4;
        f2h<<<(n4 + 255) / 256, 256>>>((const float4*)elec, (uint2*)ELh, n4);
    }
    // HX = elec @ h_w  (fp16 mma)
    {
        dim3 grid(2, N_ELEC / 64);
        gemm_h<<<grid, 256, GSM_TOT>>>(ELh, EMB, HWh, 264, nullptr, HX);
    }
    // fused fp16-mma edge kernel, all 3 types
    edge_fused<<<3 * nblk, 256, SMEM_EDGE>>>(dist[0], dist[1], dist[2],
                                             b1[0], b1[1], b1[2],
                                             HX, nuc,
                                             send[0], send[1], send[2],
                                             recv[0], recv[1], recv[2],
                                             Z, nblk);
    // Z -> fp16
    {
        int n4 = N_ELEC * 3 * KER / 4;
        f2h<<<(n4 + 255) / 256, 256>>>((const float4*)Z, (uint2*)Zh, n4);
    }
    // out = elec + Z @ Gcat  (fp16 mma)
    {
        dim3 grid(2, N_ELEC / 64);
        gemm_h<<<grid, 256, GSM_TOT>>>(Zh, 3 * KER, GTh, 776, elec, (float*)d_out);
    }
}

// round 11
// speedup vs baseline: 4.8674x; 1.5479x over previous
#include <cuda_runtime.h>
#include <cuda_fp16.h>
#include <math.h>
#include <stdint.h>

#define N_ELEC 8192
#define N_NUC  512
#define EMB    256
#define KER    256
#define DF     64
#define MID    128

// ---------------- scratch (device globals; no allocations allowed) ----------
__device__ __align__(16) float  g_HX[N_ELEC * KER];
__device__ __align__(16) float  g_Z[N_ELEC * 3 * KER];
__device__ __align__(16) __half g_Zh[N_ELEC * 3 * KER];
__device__ __align__(16) __half g_elech[N_ELEC * EMB];
// edge-kernel weight images in per-lane FRAGMENT order:
//   slot [nblk16][kstep16][lane][8 halves] = the 4 b32 regs of lane's B fragment
__device__ __align__(16) __half g_w1Th[3][128 * 64];        // 8 nblk x 4 ks
__device__ __align__(16) __half g_w2Th[3][256 * 128];       // 16 nblk x 8 ks
// gemm_h images (n-major rows, perm16'd cols)
__device__ __align__(16) __half g_hwh[256 * 264];
__device__ __align__(16) __half g_GTh[256 * 776];

// physical fragment col (within 16-block: ntp*8 + 2c + e) -> logical col 4c+2ntp+e
__device__ __host__ __forceinline__ int perm16(int n) {
    int c = (n >> 1) & 3, e = n & 1, ntp = (n >> 3) & 1;
    return (n & ~15) | (c << 2) | (ntp << 1) | e;
}

// ---------------- helpers ---------------------------------------------------
__device__ __forceinline__ void ldm_x4(uint32_t r[4], uint32_t saddr) {
    asm volatile("ldmatrix.sync.aligned.m8n8.x4.shared.b16 {%0,%1,%2,%3}, [%4];"
                 : "=r"(r[0]), "=r"(r[1]), "=r"(r[2]), "=r"(r[3]) : "r"(saddr));
}
__device__ __forceinline__ uint4 lds128(uint32_t saddr) {
    uint4 v;
    asm volatile("ld.shared.v4.b32 {%0,%1,%2,%3}, [%4];"
                 : "=r"(v.x), "=r"(v.y), "=r"(v.z), "=r"(v.w) : "r"(saddr));
    return v;
}
__device__ __forceinline__ void mma_f16(float acc[4], const uint32_t a[4],
                                        uint32_t b0, uint32_t b1) {
    asm volatile(
        "mma.sync.aligned.m16n8k16.row.col.f32.f16.f16.f32 "
        "{%0,%1,%2,%3}, {%4,%5,%6,%7}, {%8,%9}, {%0,%1,%2,%3};"
        : "+f"(acc[0]), "+f"(acc[1]), "+f"(acc[2]), "+f"(acc[3])
        : "r"(a[0]), "r"(a[1]), "r"(a[2]), "r"(a[3]), "r"(b0), "r"(b1));
}
__device__ __forceinline__ void red4(float* p, float x, float y, float z, float w) {
    asm volatile("red.global.add.v4.f32 [%0], {%1, %2, %3, %4};"
                 :: "l"(p), "f"(x), "f"(y), "f"(z), "f"(w) : "memory");
}
__device__ __forceinline__ void cp16(uint32_t saddr, const void* g) {
    asm volatile("cp.async.cg.shared.global [%0], [%1], 16;" :: "r"(saddr), "l"(g));
}
#define CP_COMMIT() asm volatile("cp.async.commit_group;" ::: "memory")
#define CP_WAIT(n)  asm volatile("cp.async.wait_group %0;" :: "n"(n) : "memory")

__device__ __forceinline__ uint32_t smem_u32(const void* p) {
    uint32_t a;
    asm("{ .reg .u64 t; cvta.to.shared.u64 t, %1; cvt.u32.u64 %0, t; }" : "=r"(a) : "l"(p));
    return a;
}
__device__ __forceinline__ uint32_t packh2(float x, float y) {   // lo=x, hi=y
    uint32_t r;
    asm("cvt.rn.f16x2.f32 %0, %1, %2;" : "=r"(r) : "f"(y), "f"(x));
    return r;
}
// fast shifted softplus: log(0.5*e^x + 0.5) via MUFU ex2/lg2.
// |x| <= ~10 for this data; result is rounded to fp16 right after, so the
// ~2^-22 approx error is invisible. Branch-free, ~4 instructions.
__device__ __forceinline__ float sspf(float x) {
    float e;
    asm("ex2.approx.f32 %0, %1;" : "=f"(e) : "f"(x * 1.4426950408889634f));
    float l;
    asm("lg2.approx.f32 %0, %1;" : "=f"(l) : "f"(fmaf(e, 0.5f, 0.5f)));
    return l * 0.69314718055994531f;
}

// ================= elementwise fp32 -> fp16 =================================
__global__ void f2h(const float4* __restrict__ src, uint2* __restrict__ dst, int n4) {
    int i = blockIdx.x * blockDim.x + threadIdx.x;
    if (i < n4) {
        float4 v = src[i];
        uint2 h;
        h.x = packh2(v.x, v.y);
        h.y = packh2(v.z, v.w);
        dst[i] = h;
    }
}

// ================= weight prep (parallel over grid.y slices) ================
__global__ void prep_weights(const float* __restrict__ w1_0, const float* __restrict__ w1_1,
                             const float* __restrict__ w1_2,
                             const float* __restrict__ w2_0, const float* __restrict__ w2_1,
                             const float* __restrict__ w2_2,
                             const float* __restrict__ g_0, const float* __restrict__ g_1,
                             const float* __restrict__ g_2,
                             const float* __restrict__ h_w)
{
    int ty = blockIdx.x;
    const float* w1 = (ty == 0) ? w1_0 : (ty == 1) ? w1_1 : w1_2;
    const float* w2 = (ty == 0) ? w2_0 : (ty == 1) ? w2_1 : w2_2;
    const float* gg = (ty == 0) ? g_0  : (ty == 1) ? g_1  : g_2;
    const int t0 = threadIdx.x + blockIdx.y * blockDim.x;
    const int stp = blockDim.x * gridDim.y;
    // w1 fragment image: MID cols NOT permuted (mreg identity needs phys order)
    for (int i = t0; i < 128 * 64; i += stp) {
        int h = i & 7, lane = (i >> 3) & 31, ks = (i >> 8) & 3, nblk = i >> 10;
        int gl = lane >> 2, cl = lane & 3, reg = h >> 1, e = h & 1;
        int k = ks * 16 + (reg & 1) * 8 + 2 * cl + e;
        int n = nblk * 16 + (reg >> 1) * 8 + gl;
        g_w1Th[ty][i] = __float2half(w1[k * 128 + n]);
    }
    // w2 fragment image: KER cols perm16'd (epilogue red.v4 contiguity)
    for (int i = t0; i < 256 * 128; i += stp) {
        int h = i & 7, lane = (i >> 3) & 31, ks = (i >> 8) & 7, nblk = i >> 11;
        int gl = lane >> 2, cl = lane & 3, reg = h >> 1, e = h & 1;
        int k = ks * 16 + (reg & 1) * 8 + 2 * cl + e;
        int n = nblk * 16 + perm16((reg >> 1) * 8 + gl);
        g_w2Th[ty][i] = __float2half(w2[k * 256 + n]);
    }
    // Gcat^T image (EMB cols permuted) — gemm_h scheme
    for (int i = t0; i < 256 * 256; i += stp) {
        int n = i >> 8, kk = i & 255;
        g_GTh[n * 776 + ty * 256 + kk] = __float2half(gg[kk * 256 + perm16(n)]);
    }
    if (ty == 0)
        for (int i = t0; i < 256 * 256; i += stp) {
            int n = i >> 8, k = i & 255;
            g_hwh[n * 264 + k] = __float2half(h_w[k * 256 + perm16(n)]);
        }
}

// ================= fp16 tensor-core GEMM ====================================
#define GSM_A0 0
#define GSM_A1 9216
#define GSM_B0 18432
#define GSM_B1 36864
#define GSM_TOT 55296

__global__ void __launch_bounds__(256, 3)
gemm_h(const __half* __restrict__ A, int K,
       const __half* __restrict__ B, int Kpad,
       const float* __restrict__ Cin, float* __restrict__ Out)
{
    extern __shared__ char smem[];
    const uint32_t sbase = smem_u32(smem);
    const int t = threadIdx.x, warp = t >> 5, lane = t & 31;
    const int wm = warp & 3, wn = warp >> 2;
    const int g = lane >> 2, c = lane & 3;
    const int n0 = blockIdx.x * 128, m0 = blockIdx.y * 64;
    const int nch = K / 64;

    const int lrowA = (lane & 7) + ((lane >> 3) & 1) * 8;
    const int lkA   = (lane >> 4) * 8;
    const int lrowB = ((lane >> 4) << 3) + (lane & 7);
    const int lkB   = ((lane >> 3) & 1) * 8;

    float acc[8][4];
#pragma unroll
    for (int j = 0; j < 8; j++)
#pragma unroll
        for (int p = 0; p < 4; p++) acc[j][p] = 0.f;

#define LOAD_CHUNK(ch) do {                                                     \
        uint32_t abuf = sbase + (((ch) & 1) ? GSM_A1 : GSM_A0);                 \
        uint32_t bbuf = sbase + (((ch) & 1) ? GSM_B1 : GSM_B0);                 \
        const char* ag = (const char*)(A + (long)m0 * K + (ch) * 64);           \
        _Pragma("unroll")                                                       \
        for (int i = 0; i < 2; i++) {                                           \
            int idx = t + 256 * i, row = idx >> 3, cc = idx & 7;                \
            cp16(abuf + row * 144 + cc * 16, ag + (long)row * K * 2 + cc * 16); \
        }                                                                       \
        const char* bg = (const char*)(B + (long)n0 * Kpad + (ch) * 64);        \
        _Pragma("unroll")                                                       \
        for (int i = 0; i < 4; i++) {                                           \
            int idx = t + 256 * i, row = idx >> 3, cc = idx & 7;                \
            cp16(bbuf + row * 144 + cc * 16, bg + (long)row * Kpad * 2 + cc * 16); \
        }                                                                       \
        CP_COMMIT();                                                            \
    } while (0)

    LOAD_CHUNK(0);
    for (int ch = 0; ch < nch; ch++) {
        if (ch + 1 < nch) { LOAD_CHUNK(ch + 1); CP_WAIT(1); }
        else              { CP_WAIT(0); }
        __syncthreads();
        uint32_t abuf = sbase + ((ch & 1) ? GSM_A1 : GSM_A0);
        uint32_t bbuf = sbase + ((ch & 1) ? GSM_B1 : GSM_B0);
        uint32_t aB = abuf + (wm * 16 + lrowA) * 144 + lkA * 2;
        uint32_t bB = bbuf + (wn * 64 + lrowB) * 144 + lkB * 2;
#pragma unroll
        for (int s = 0; s < 4; s++) {
            uint32_t a[4];
            ldm_x4(a, aB + s * 32);
#pragma unroll
            for (int p = 0; p < 4; p++) {
                uint32_t b[4];
                ldm_x4(b, bB + p * 16 * 144 + s * 32);
                mma_f16(acc[2 * p],     a, b[0], b[1]);
                mma_f16(acc[2 * p + 1], a, b[2], b[3]);
            }
        }
        __syncthreads();
    }

    int ra = m0 + wm * 16 + g, rb = ra + 8;
#pragma unroll
    for (int p = 0; p < 4; p++) {
        int col = n0 + wn * 64 + p * 16 + 4 * c;
        float4 v0 = make_float4(acc[2*p][0], acc[2*p][1], acc[2*p+1][0], acc[2*p+1][1]);
        float4 v1 = make_float4(acc[2*p][2], acc[2*p][3], acc[2*p+1][2], acc[2*p+1][3]);
        if (Cin) {
            float4 c0 = *(const float4*)(Cin + (long)ra * 256 + col);
            float4 c1 = *(const float4*)(Cin + (long)rb * 256 + col);
            v0.x += c0.x; v0.y += c0.y; v0.z += c0.z; v0.w += c0.w;
            v1.x += c1.x; v1.y += c1.y; v1.z += c1.z; v1.w += c1.w;
        }
        *(float4*)(Out + (long)ra * 256 + col) = v0;
        *(float4*)(Out + (long)rb * 256 + col) = v1;
    }
}

// ================= fused fp16 mma edge kernel ===============================
#define SH_B1    0
#define SH_SEND  512
#define SH_RECV  1024
#define SH_DIST  1536
#define SH_W1T   19968
#define SH_W2A   36352
#define SH_W2B   52736
#define SMEM_EDGE 69120

__global__ void __launch_bounds__(256, 3)
edge_fused(const float* __restrict__ dist0, const float* __restrict__ dist1,
           const float* __restrict__ dist2,
           const float* __restrict__ b1_0, const float* __restrict__ b1_1,
           const float* __restrict__ b1_2,
           const float* __restrict__ HX, const float* __restrict__ nuc,
           const int* __restrict__ s0, const int* __restrict__ s1, const int* __restrict__ s2,
           const int* __restrict__ r0p, const int* __restrict__ r1p, const int* __restrict__ r2p,
           float* __restrict__ Z, int nblk)
{
    extern __shared__ char smem[];
    float* smF = (float*)smem;
    const uint32_t sbase = smem_u32(smem);
    const int t = threadIdx.x, warp = t >> 5, lane = t & 31;
    const int g = lane >> 2, c = lane & 3;
    const int wr0 = warp * 16;

    const int ty  = blockIdx.x / nblk;
    const int blk = blockIdx.x - ty * nblk;
    const float* dist  = (ty == 0) ? dist0 : (ty == 1) ? dist1 : dist2;
    const float* b1    = (ty == 0) ? b1_0  : (ty == 1) ? b1_1  : b1_2;
    const int*   snd   = (ty == 0) ? s0 : (ty == 1) ? s1 : s2;
    const int*   rcv   = (ty == 0) ? r0p : (ty == 1) ? r1p : r2p;
    const float* hxsrc = (ty == 2) ? nuc : HX;
    const int    zoff  = ty * KER;
    const long   e0    = (long)blk * 128;
    const __half* w1T  = g_w1Th[ty];
    const __half* w2T  = g_w2Th[ty];

    // ---- fill ----
    if (t < 128) {
        smF[(SH_B1 >> 2) + t] = b1[t];
        ((int*)smem)[(SH_SEND >> 2) + t] = snd[e0 + t];
        ((int*)smem)[(SH_RECV >> 2) + t] = rcv[e0 + t];
    }
    {
        int row = t >> 1, part = t & 1;
        const float4* dr = (const float4*)(dist + (e0 + row) * DF);
        char* dst = smem + SH_DIST + row * 144;
#pragma unroll
        for (int j = 0; j < 8; j++) {
            int c4 = part * 8 + j;
            float4 v = dr[c4];
            uint2 h;
            h.x = packh2(v.x, v.y);
            h.y = packh2(v.z, v.w);
            *(uint2*)(dst + c4 * 8) = h;
        }
    }
#pragma unroll
    for (int i = 0; i < 4; i++)
        cp16(sbase + SH_W1T + (t + 256 * i) * 16, (const char*)w1T + (t + 256 * i) * 16);
    CP_COMMIT();
#pragma unroll
    for (int i = 0; i < 4; i++)
        cp16(sbase + SH_W2A + (t + 256 * i) * 16, (const char*)w2T + (t + 256 * i) * 16);
    CP_COMMIT();

    CP_WAIT(1);
    __syncthreads();

    const int lrowA = (lane & 7) + ((lane >> 3) & 1) * 8;
    const int lkA   = (lane >> 4) * 8;
    const uint32_t aBase = sbase + SH_DIST + (wr0 + lrowA) * 144 + lkA * 2;
    const uint32_t w1s   = sbase + SH_W1T + lane * 16;

    // ---- stage 1 ----
    uint32_t mreg[8][4];
#pragma unroll
    for (int pass = 0; pass < 2; pass++) {
        float acc[8][4];
#pragma unroll
        for (int j = 0; j < 8; j++)
#pragma unroll
            for (int q = 0; q < 4; q++) acc[j][q] = 0.f;
#pragma unroll
        for (int s = 0; s < 4; s++) {
            uint32_t a[4];
            ldm_x4(a, aBase + s * 32);
#pragma unroll
            for (int p = 0; p < 4; p++) {
                uint4 b = lds128(w1s + ((pass * 4 + p) * 4 + s) * 512);
                mma_f16(acc[2 * p],     a, b.x, b.y);
                mma_f16(acc[2 * p + 1], a, b.z, b.w);
            }
        }
        const float* sB1 = smF + (SH_B1 >> 2);
#pragma unroll
        for (int p = 0; p < 4; p++) {
            int nt0 = pass * 8 + 2 * p, nt1 = nt0 + 1;
            float bA0 = sB1[nt0 * 8 + 2 * c], bA1 = sB1[nt0 * 8 + 2 * c + 1];
            float bB0 = sB1[nt1 * 8 + 2 * c], bB1 = sB1[nt1 * 8 + 2 * c + 1];
            int s2i = pass * 4 + p;
            mreg[s2i][0] = packh2(sspf(acc[2*p][0] + bA0),   sspf(acc[2*p][1] + bA1));
            mreg[s2i][1] = packh2(sspf(acc[2*p][2] + bA0),   sspf(acc[2*p][3] + bA1));
            mreg[s2i][2] = packh2(sspf(acc[2*p+1][0] + bB0), sspf(acc[2*p+1][1] + bB1));
            mreg[s2i][3] = packh2(sspf(acc[2*p+1][2] + bB0), sspf(acc[2*p+1][3] + bB1));
        }
    }

    const int ra = wr0 + g, rb = wr0 + g + 8;
    const int sa = ((int*)smem)[(SH_SEND >> 2) + ra];
    const int sb = ((int*)smem)[(SH_SEND >> 2) + rb];
    const int qa = ((int*)smem)[(SH_RECV >> 2) + ra];
    const int qb = ((int*)smem)[(SH_RECV >> 2) + rb];
    const float* hxa = hxsrc + (long)sa * KER;
    const float* hxb = hxsrc + (long)sb * KER;
    float* Za = Z + (long)qa * (3 * KER) + zoff;
    float* Zb = Z + (long)qb * (3 * KER) + zoff;

    CP_WAIT(0);
    __syncthreads();

    // ---- stage 2 ----
#pragma unroll
    for (int q = 0; q < 4; q++) {
        if (q < 3) {
            uint32_t dstq = sbase + (((q + 1) & 1) ? SH_W2B : SH_W2A);
            const char* srcq = (const char*)(w2T + (long)(q + 1) * 64 * 128);
#pragma unroll
            for (int i = 0; i < 4; i++)
                cp16(dstq + (t + 256 * i) * 16, srcq + (t + 256 * i) * 16);
            CP_COMMIT();
        }
        const uint32_t swq = sbase + ((q & 1) ? SH_W2B : SH_W2A) + lane * 16;
#pragma unroll
        for (int nb = 0; nb < 4; nb++) {
            float acc2[2][4];
#pragma unroll
            for (int j = 0; j < 2; j++)
#pragma unroll
                for (int p = 0; p < 4; p++) acc2[j][p] = 0.f;
#pragma unroll
            for (int s = 0; s < 8; s++) {
                uint4 b = lds128(swq + (nb * 8 + s) * 512);
                mma_f16(acc2[0], mreg[s], b.x, b.y);
                mma_f16(acc2[1], mreg[s], b.z, b.w);
            }
            int base = q * 64 + nb * 16 + 4 * c;
            float4 ha = *(const float4*)(hxa + base);
            red4(Za + base, acc2[0][0] * ha.x, acc2[0][1] * ha.y,
                            acc2[1][0] * ha.z, acc2[1][1] * ha.w);
            float4 hb = *(const float4*)(hxb + base);
            red4(Zb + base, acc2[0][2] * hb.x, acc2[0][3] * hb.y,
                            acc2[1][2] * hb.z, acc2[1][3] * hb.w);
        }
        CP_WAIT(0);
        __syncthreads();
    }
}

// ---------------- launcher --------------------------------------------------
extern "C" void kernel_launch(void* const* d_in, const int* in_sizes, int n_in,
                              void* d_out, int out_size)
{
    const float* elec = (const float*)d_in[0];
    const float* nuc  = (const float*)d_in[1];
    const float *dist[3], *w1[3], *b1[3], *w2[3], *g[3];

    bool dictOrder = (in_sizes[3] == DF * MID);
    if (dictOrder) {
        const int base[3] = {2, 7, 12};
        for (int tI = 0; tI < 3; tI++) {
            dist[tI] = (const float*)d_in[base[tI] + 0];
            w1[tI]   = (const float*)d_in[base[tI] + 1];
            b1[tI]   = (const float*)d_in[base[tI] + 2];
            w2[tI]   = (const float*)d_in[base[tI] + 3];
            g[tI]    = (const float*)d_in[base[tI] + 4];
        }
    } else {
        for (int tI = 0; tI < 3; tI++) {
            dist[tI] = (const float*)d_in[2 + tI];
            w1[tI]   = (const float*)d_in[5 + 3 * tI];
            b1[tI]   = (const float*)d_in[6 + 3 * tI];
            w2[tI]   = (const float*)d_in[7 + 3 * tI];
            g[tI]    = (const float*)d_in[14 + tI];
        }
    }
    const float* h_w     = (const float*)d_in[17];
    const int*   send[3] = {(const int*)d_in[18], (const int*)d_in[19], (const int*)d_in[20]};
    const int*   recv[3] = {(const int*)d_in[21], (const int*)d_in[22], (const int*)d_in[23]};
    const int    E = in_sizes[2] / DF;
    const int    nblk = E / 128;

    float *HX, *Z;
    __half *Zh, *ELh, *HWh, *GTh;
    cudaGetSymbolAddress((void**)&HX,  g_HX);
    cudaGetSymbolAddress((void**)&Z,   g_Z);
    cudaGetSymbolAddress((void**)&Zh,  g_Zh);
    cudaGetSymbolAddress((void**)&ELh, g_elech);
    cudaGetSymbolAddress((void**)&HWh, g_hwh);
    cudaGetSymbolAddress((void**)&GTh, g_GTh);

    cudaFuncSetAttribute(edge_fused, cudaFuncAttributeMaxDynamicSharedMemorySize, SMEM_EDGE);
    cudaFuncSetAttribute(gemm_h, cudaFuncAttributeMaxDynamicSharedMemorySize, GSM_TOT);

    cudaMemsetAsync(Z, 0, sizeof(float) * N_ELEC * 3 * KER);

    // weight prep spread over 48 CTAs (was 3 — serial tail on 3 SMs)
    prep_weights<<<dim3(3, 16), 256>>>(w1[0], w1[1], w1[2], w2[0], w2[1], w2[2],
                                       g[0], g[1], g[2], h_w);

    // electrons -> fp16
    {
        int n4 = N_ELEC * EMB / 4;
        f2h<<<(n4 + 255) / 256, 256>>>((const float4*)elec, (uint2*)ELh, n4);
    }
    // HX = elec @ h_w  (fp16 mma)
    {
        dim3 grid(2, N_ELEC / 64);
        gemm_h<<<grid, 256, GSM_TOT>>>(ELh, EMB, HWh, 264, nullptr, HX);
    }
    // fused fp16-mma edge kernel, all 3 types
    edge_fused<<<3 * nblk, 256, SMEM_EDGE>>>(dist[0], dist[1], dist[2],
                                             b1[0], b1[1], b1[2],
                                             HX, nuc,
                                             send[0], send[1], send[2],
                                             recv[0], recv[1], recv[2],
                                             Z, nblk);
    // Z -> fp16
    {
        int n4 = N_ELEC * 3 * KER / 4;
        f2h<<<(n4 + 255) / 256, 256>>>((const float4*)Z, (uint2*)Zh, n4);
    }
    // out = elec + Z @ Gcat  (fp16 mma)
    {
        dim3 grid(2, N_ELEC / 64);
        gemm_h<<<grid, 256, GSM_TOT>>>(Zh, 3 * KER, GTh, 776, elec, (float*)d_out);
    }
}